// round 12
// baseline (speedup 1.0000x reference)
#include <cuda_runtime.h>
#include <cuda_bf16.h>
#include <mma.h>
#include <math.h>
#include <stdint.h>

using namespace nvcuda;

// Problem constants
#define BB  64
#define TT  12
#define NN  325
#define DIN 2
#define HH  128
#define KF  5

#define NB      (NN*BB)          // 20800
#define CP0     144              // padded C for layer0 (130 -> 144)
#define CP1     256              // layer1 C
#define KTB0    192              // weight K rows per plane, layer0 (ceil64(144))
#define KTB1    256

#define PSTR0   (384LL*64*144)   // feats plane stride layer0
#define PSTR1   (384LL*64*256)

// ---------------- static scratch (pads never written => stay zero) ----------
__device__ __align__(256) __nv_bfloat16 g_f0h[5*PSTR0], g_f0l[5*PSTR0];
__device__ __align__(256) __nv_bfloat16 g_f1h[5*PSTR1], g_f1l[5*PSTR1];
__device__ __align__(256) __nv_bfloat16 g_sh[2*384*384], g_sl[2*384*384];
__device__ __align__(256) __nv_bfloat16 g_wh[1720320],   g_wl[1720320];
__device__ float g_gates[(long long)NB*2*HH];
__device__ float g_h0[(long long)NB*HH];
__device__ float g_h1[(long long)NB*HH];
__device__ float g_xdec[(long long)NB*DIN];

static __nv_bfloat16 *g_sh_p = nullptr, *g_sl_p = nullptr;

// weight pool offsets (KF * KTB * out elements each)
#define OFF_E0G 0
#define OFF_E0C 245760
#define OFF_E1G 368640
#define OFF_E1C 696320
#define OFF_D0G 860160
#define OFF_D0C 1105920
#define OFF_D1G 1228800
#define OFF_D1C 1556480

// ---------------------------------------------------------------------------
// helpers / prep
// ---------------------------------------------------------------------------
__device__ __forceinline__ void split2(float v, __nv_bfloat16& hi, __nv_bfloat16& lo) {
    hi = __float2bfloat16_rn(v);
    lo = __float2bfloat16_rn(v - __bfloat162float(hi));
}
__device__ __forceinline__ void cp16(uint32_t s, const void* g) {
    asm volatile("cp.async.cg.shared.global [%0], [%1], 16;\n" :: "r"(s), "l"(g));
}

__global__ void split_sup_kernel(const float* __restrict__ sup) {
    int i = blockIdx.x * blockDim.x + threadIdx.x;
    if (i >= 2 * NN * NN) return;
    int s = i / (NN * NN), r = (i / NN) % NN, c = i % NN;
    __nv_bfloat16 hi, lo; split2(sup[i], hi, lo);
    long long d = (long long)s * 384 * 384 + (long long)r * 384 + c;
    g_sh[d] = hi; g_sl[d] = lo;
}

struct WSpec8 { const float* src[8]; long long off[8]; int C[8], KTB[8], outN[8]; };
__global__ void split_w_kernel(WSpec8 ws, __nv_bfloat16* dh, __nv_bfloat16* dl) {
    int z = blockIdx.z;
    const float* W = ws.src[z];
    int C = ws.C[z], KTB = ws.KTB[z], outN = ws.outN[z];
    long long total = (long long)KF * C * outN;
    for (long long i = blockIdx.x * (long long)blockDim.x + threadIdx.x; i < total;
         i += (long long)gridDim.x * blockDim.x) {
        int p = (int)(i / ((long long)C * outN));
        int rem = (int)(i % ((long long)C * outN));
        int k = rem / outN, o = rem % outN;
        __nv_bfloat16 hi, lo; split2(W[i], hi, lo);
        long long d = ws.off[z] + ((long long)p * KTB + k) * outN + o;
        dh[d] = hi; dl[d] = lo;
    }
}

__global__ void zero3_kernel(float* a, long long na, float* b, long long nb2,
                             float* c, long long nc) {
    long long tot = na + nb2 + nc;
    for (long long i = blockIdx.x * (long long)blockDim.x + threadIdx.x; i < tot;
         i += (long long)gridDim.x * blockDim.x) {
        if (i < na) a[i] = 0.f;
        else if (i < na + nb2) b[i - na] = 0.f;
        else c[i - na - nb2] = 0.f;
    }
}

// ---------------------------------------------------------------------------
// Pipelined bf16-pair GEMM, 128x128 block tile, BK=64, 8 warps (2x4),
// warp tile 64x32, 3-MMA hi/lo emulation, cp.async double buffer.
//   C = act( sum_p A_p[MxKt] @ B_p[KtxN] + bias )
// act: 0 = pair out (Ch/Cl), 1 = sigmoid->Cf, 2 = tanh->Cf,
//      3 = tanh + GRU fuse: Cf = z*Cf + (1-z)*tanh(v),  z from gIn[m*256+col]
// ---------------------------------------------------------------------------
#define SMA_BUF 18432                 // 128 * 72 * 2B
#define SMB_BUF 17408                 // 64 * 136 * 2B
#define SMEM_A_BYTES (4*SMA_BUF)      // 2 stages * 2 (hi/lo)
#define SMEM_B_BYTES (4*SMB_BUF)
#define SMEM_TOTAL   (SMEM_A_BYTES + SMEM_B_BYTES)   // 143360

__global__ __launch_bounds__(256, 1) void pgemm_kernel(
    int M, int Kt, int ktpp, int nplanes,
    const __nv_bfloat16* __restrict__ Ah, const __nv_bfloat16* __restrict__ Al,
    long long lda, long long pstrA, long long aZ,
    const __nv_bfloat16* __restrict__ Bh, const __nv_bfloat16* __restrict__ Bl,
    long long ldb, long long pstrB, long long bZ,
    float* __restrict__ Cf, __nv_bfloat16* __restrict__ Ch, __nv_bfloat16* __restrict__ Cl,
    long long ldc, long long cZ,
    const float* __restrict__ bias, int act, const float* __restrict__ gIn)
{
    extern __shared__ char smem[];
    __nv_bfloat16* sA = (__nv_bfloat16*)smem;
    __nv_bfloat16* sB = (__nv_bfloat16*)(smem + SMEM_A_BYTES);
    const uint32_t sAu = (uint32_t)__cvta_generic_to_shared(sA);
    const uint32_t sBu = (uint32_t)__cvta_generic_to_shared(sB);

    const int tid = threadIdx.x;
    const int w = tid >> 5, lane = tid & 31;
    const int wm = w >> 2, wn = w & 3;           // 2 x 4 warps, 64x32 tiles
    const int rowBase = blockIdx.y * 128;
    const int colBase = blockIdx.x * 128;

    Ah += (long long)blockIdx.z * aZ;  Al += (long long)blockIdx.z * aZ;
    Bh += (long long)blockIdx.z * bZ;  Bl += (long long)blockIdx.z * bZ;
    if (Ch) { Ch += (long long)blockIdx.z * cZ; Cl += (long long)blockIdx.z * cZ; }
    if (Cf) { Cf += (long long)blockIdx.z * cZ; }

    auto fill = [&](int stage, int it) {
        int p = it / ktpp;
        int k0 = (it - p * ktpp) * 64;
        const __nv_bfloat16* A0h = Ah + (long long)p * pstrA;
        const __nv_bfloat16* A0l = Al + (long long)p * pstrA;
        const __nv_bfloat16* B0h = Bh + (long long)p * pstrB;
        const __nv_bfloat16* B0l = Bl + (long long)p * pstrB;
        // A: 128 rows x 64 k = 1024 16B chunks per hi/lo
#pragma unroll
        for (int t = 0; t < 4; ++t) {
            int id = tid + t * 256;
            int row = id >> 3, cc = id & 7;
            int k = k0 + cc * 8;
            uint32_t s0 = sAu + (uint32_t)((stage * 2 + 0) * SMA_BUF + (row * 72 + cc * 8) * 2);
            uint32_t s1 = sAu + (uint32_t)((stage * 2 + 1) * SMA_BUF + (row * 72 + cc * 8) * 2);
            if (k < Kt) {
                long long ga = (long long)(rowBase + row) * lda + k;
                cp16(s0, A0h + ga);
                cp16(s1, A0l + ga);
            } else {
                float4 z = {0.f, 0.f, 0.f, 0.f};
                *(float4*)((char*)sA + (stage * 2 + 0) * SMA_BUF + (row * 72 + cc * 8) * 2) = z;
                *(float4*)((char*)sA + (stage * 2 + 1) * SMA_BUF + (row * 72 + cc * 8) * 2) = z;
            }
        }
        // B: 64 k x 128 cols = 1024 16B chunks per hi/lo
#pragma unroll
        for (int t = 0; t < 4; ++t) {
            int id = tid + t * 256;
            int row = id >> 4, cc = id & 15;
            long long gb = (long long)(k0 + row) * ldb + colBase + cc * 8;
            uint32_t s0 = sBu + (uint32_t)((stage * 2 + 0) * SMB_BUF + (row * 136 + cc * 8) * 2);
            uint32_t s1 = sBu + (uint32_t)((stage * 2 + 1) * SMB_BUF + (row * 136 + cc * 8) * 2);
            cp16(s0, B0h + gb);
            cp16(s1, B0l + gb);
        }
        asm volatile("cp.async.commit_group;\n" ::: "memory");
    };

    wmma::fragment<wmma::accumulator, 16, 16, 16, float> acc[4][2];
#pragma unroll
    for (int i = 0; i < 4; ++i)
#pragma unroll
        for (int j = 0; j < 2; ++j) wmma::fill_fragment(acc[i][j], 0.f);

    const int T = ktpp * nplanes;
    fill(0, 0);
    for (int it = 0; it < T; ++it) {
        if (it + 1 < T) {
            fill((it + 1) & 1, it + 1);
            asm volatile("cp.async.wait_group 1;\n" ::: "memory");
        } else {
            asm volatile("cp.async.wait_group 0;\n" ::: "memory");
        }
        __syncthreads();
        const int st = it & 1;
        __nv_bfloat16* cAh = sA + (st * 2 + 0) * (SMA_BUF / 2);
        __nv_bfloat16* cAl = sA + (st * 2 + 1) * (SMA_BUF / 2);
        __nv_bfloat16* cBh = sB + (st * 2 + 0) * (SMB_BUF / 2);
        __nv_bfloat16* cBl = sB + (st * 2 + 1) * (SMB_BUF / 2);
#pragma unroll 1
        for (int kk = 0; kk < 4; ++kk) {
            wmma::fragment<wmma::matrix_a, 16, 16, 16, __nv_bfloat16, wmma::row_major> a_h[4], a_l[4];
            wmma::fragment<wmma::matrix_b, 16, 16, 16, __nv_bfloat16, wmma::row_major> b_h[2], b_l[2];
#pragma unroll
            for (int i = 0; i < 4; ++i) {
                const int r = wm * 64 + i * 16;
                wmma::load_matrix_sync(a_h[i], cAh + r * 72 + kk * 16, 72);
                wmma::load_matrix_sync(a_l[i], cAl + r * 72 + kk * 16, 72);
            }
#pragma unroll
            for (int j = 0; j < 2; ++j) {
                const int c = wn * 32 + j * 16;
                wmma::load_matrix_sync(b_h[j], cBh + (kk * 16) * 136 + c, 136);
                wmma::load_matrix_sync(b_l[j], cBl + (kk * 16) * 136 + c, 136);
            }
#pragma unroll
            for (int i = 0; i < 4; ++i)
#pragma unroll
                for (int j = 0; j < 2; ++j) {
                    wmma::mma_sync(acc[i][j], a_h[i], b_h[j], acc[i][j]);
                    wmma::mma_sync(acc[i][j], a_h[i], b_l[j], acc[i][j]);
                    wmma::mma_sync(acc[i][j], a_l[i], b_h[j], acc[i][j]);
                }
        }
        __syncthreads();
    }

    // ---- epilogue: per-warp 16x20 fp32 scratch round-trip ----
    float* scr = (float*)smem + w * (16 * 20);
#pragma unroll 1
    for (int i = 0; i < 4; ++i)
#pragma unroll 1
        for (int j = 0; j < 2; ++j) {
            wmma::store_matrix_sync(scr, acc[i][j], 20, wmma::mem_row_major);
            __syncwarp();
#pragma unroll
            for (int t = 0; t < 4; ++t) {
                int pr = t * 32 + lane;            // 0..127 pairs
                int r = pr >> 3, c = (pr & 7) * 2;
                int gr = rowBase + wm * 64 + i * 16 + r;
                if (gr < M) {
                    int gc = colBase + wn * 32 + j * 16 + c;
                    float v0 = scr[r * 20 + c];
                    float v1 = scr[r * 20 + c + 1];
                    if (bias) { v0 += bias[gc]; v1 += bias[gc + 1]; }
                    if (act == 1) {
                        v0 = 1.f / (1.f + expf(-v0)); v1 = 1.f / (1.f + expf(-v1));
                    } else if (act == 2) {
                        v0 = tanhf(v0); v1 = tanhf(v1);
                    } else if (act == 3) {
                        v0 = tanhf(v0); v1 = tanhf(v1);
                        float z0 = gIn[(long long)gr * (2 * HH) + gc];
                        float z1 = gIn[(long long)gr * (2 * HH) + gc + 1];
                        long long ho = (long long)gr * ldc + gc;
                        v0 = z0 * Cf[ho]     + (1.f - z0) * v0;
                        v1 = z1 * Cf[ho + 1] + (1.f - z1) * v1;
                    }
                    if (Ch) {
                        __nv_bfloat16 h0b, l0b, h1b, l1b;
                        split2(v0, h0b, l0b); split2(v1, h1b, l1b);
                        __nv_bfloat162 hh; hh.x = h0b; hh.y = h1b;
                        __nv_bfloat162 ll; ll.x = l0b; ll.y = l1b;
                        *(__nv_bfloat162*)&Ch[(long long)gr * ldc + gc] = hh;
                        *(__nv_bfloat162*)&Cl[(long long)gr * ldc + gc] = ll;
                    } else {
                        float2 f; f.x = v0; f.y = v1;
                        *(float2*)&Cf[(long long)gr * ldc + gc] = f;
                    }
                }
            }
            __syncwarp();
        }
}

// ---------------------------------------------------------------------------
// concat: plane 0 of feats (hi/lo): [x, (r*)h], zeros in pad columns
// ---------------------------------------------------------------------------
__global__ void concat_kernel(__nv_bfloat16* __restrict__ ph,
                              __nv_bfloat16* __restrict__ pl,
                              const float* __restrict__ xsrc, int xmode, int t,
                              int Cx, int C, int Cp,
                              const float* __restrict__ h,
                              const float* __restrict__ gates, int useR)
{
    const long long total = (long long)NB * Cp;
    for (long long i = blockIdx.x * (long long)blockDim.x + threadIdx.x; i < total;
         i += (long long)gridDim.x * blockDim.x) {
        int c = (int)(i % Cp), nb = (int)(i / Cp);
        float v = 0.f;
        if (c < Cx) {
            if (xmode == 0) {
                int b = nb % BB, n = nb / BB;
                v = xsrc[(((long long)b * TT + t) * NN + n) * DIN + c];
            } else v = xsrc[(long long)nb * Cx + c];
        } else if (c < C) {
            int hc = c - Cx;
            float hv = h[(long long)nb * HH + hc];
            if (useR) hv *= gates[(long long)nb * (2 * HH) + HH + hc];
            v = hv;
        }
        __nv_bfloat16 hi, lo; split2(v, hi, lo);
        ph[i] = hi; pl[i] = lo;
    }
}

__global__ void dec_proj_kernel(const float* __restrict__ h1,
                                const float* __restrict__ Wp,
                                const float* __restrict__ bp,
                                float* __restrict__ out,
                                float* __restrict__ xdec, int t)
{
    int row = blockIdx.x * blockDim.x + threadIdx.x;
    if (row >= NB) return;
    int n = row / BB, b = row % BB;
    float a0 = bp[0], a1 = bp[1];
    const float* hr = h1 + (long long)row * HH;
#pragma unroll 8
    for (int k = 0; k < HH; ++k) {
        float hv = hr[k];
        a0 += hv * Wp[k * 2]; a1 += hv * Wp[k * 2 + 1];
    }
    long long o = (((long long)b * TT + t) * NN + n) * 2;
    out[o] = a0; out[o + 1] = a1;
    xdec[(long long)row * 2] = a0; xdec[(long long)row * 2 + 1] = a1;
}

// ---------------------------------------------------------------------------
// host
// ---------------------------------------------------------------------------
static inline int gblocks(long long total, int tpb) {
    long long b = (total + tpb - 1) / tpb;
    if (b > 1048576) b = 1048576;
    return (int)b;
}

struct CellW {
    const __nv_bfloat16 *wgh, *wgl, *wch, *wcl;
    const float *bg, *bc;
    int Cx, Cp, ktpp, KTB;
    __nv_bfloat16 *fh, *fl;
    long long pstr;
};

static float* G_gates;

static void run_cell(const float* xsrc, int xmode, int t, float* h, const CellW& cw)
{
    const int Cp = cw.Cp, C = cw.Cx + HH;
    const int ldN = BB * Cp;
    const long long PS = cw.pstr;
    const long long SUPZ = 384LL * 384;

    dim3 gd(ldN / 128, 3, 2);     // diffusion: 128x128 tiles, M=384 -> 3 y

    auto diffuse = [&](const __nv_bfloat16* srcH, const __nv_bfloat16* srcL,
                       long long bZ, __nv_bfloat16* dstH, __nv_bfloat16* dstL) {
        pgemm_kernel<<<gd, 256, SMEM_TOTAL>>>(
            NN, 384, 6, 1,
            g_sh_p, g_sl_p, 384, 0, SUPZ,
            srcH, srcL, ldN, 0, bZ,
            nullptr, dstH, dstL, ldN, 2 * PS,
            nullptr, 0, nullptr);
    };

    for (int pass = 0; pass < 2; ++pass) {
        concat_kernel<<<gblocks((long long)NB * Cp, 256), 256>>>(
            cw.fh, cw.fl, xsrc, xmode, t, cw.Cx, C, Cp, h, G_gates, pass);
        diffuse(cw.fh, cw.fl, 0, cw.fh + PS, cw.fl + PS);
        diffuse(cw.fh + PS, cw.fl + PS, 2 * PS, cw.fh + 2 * PS, cw.fl + 2 * PS);
        if (pass == 0) {
            dim3 g(2, (NB + 127) / 128, 1);
            pgemm_kernel<<<g, 256, SMEM_TOTAL>>>(
                NB, Cp, cw.ktpp, KF,
                cw.fh, cw.fl, Cp, PS, 0,
                cw.wgh, cw.wgl, 2 * HH, (long long)cw.KTB * 2 * HH, 0,
                G_gates, nullptr, nullptr, 2 * HH, 0,
                cw.bg, 1, nullptr);
        } else {
            dim3 g(1, (NB + 127) / 128, 1);
            pgemm_kernel<<<g, 256, SMEM_TOTAL>>>(
                NB, Cp, cw.ktpp, KF,
                cw.fh, cw.fl, Cp, PS, 0,
                cw.wch, cw.wcl, HH, (long long)cw.KTB * HH, 0,
                h, nullptr, nullptr, HH, 0,
                cw.bc, 3, G_gates);
        }
    }
}

extern "C" void kernel_launch(void* const* d_in, const int* in_sizes, int n_in,
                              void* d_out, int out_size)
{
    const float* source   = (const float*)d_in[0];
    const float* supports = (const float*)d_in[2];
    const float* Wp = (const float*)d_in[19];
    const float* bp = (const float*)d_in[20];
    float* out = (float*)d_out;

    cudaFuncSetAttribute(pgemm_kernel, cudaFuncAttributeMaxDynamicSharedMemorySize,
                         SMEM_TOTAL);

    __nv_bfloat16 *f0h, *f0l, *f1h, *f1l, *wh, *wl;
    float *h0, *h1, *xdec;
    cudaGetSymbolAddress((void**)&f0h, g_f0h);
    cudaGetSymbolAddress((void**)&f0l, g_f0l);
    cudaGetSymbolAddress((void**)&f1h, g_f1h);
    cudaGetSymbolAddress((void**)&f1l, g_f1l);
    cudaGetSymbolAddress((void**)&g_sh_p, g_sh);
    cudaGetSymbolAddress((void**)&g_sl_p, g_sl);
    cudaGetSymbolAddress((void**)&wh, g_wh);
    cudaGetSymbolAddress((void**)&wl, g_wl);
    cudaGetSymbolAddress((void**)&G_gates, g_gates);
    cudaGetSymbolAddress((void**)&h0, g_h0);
    cudaGetSymbolAddress((void**)&h1, g_h1);
    cudaGetSymbolAddress((void**)&xdec, g_xdec);

    // ---- prep: exactly 3 launches so launch #6 is a diffusion GEMM ----
    split_sup_kernel<<<gblocks(2LL * NN * NN, 256), 256>>>(supports);
    WSpec8 ws;
    const int  idx[8]  = {3, 5, 7, 9, 11, 13, 15, 17};
    const long long off[8] = {OFF_E0G, OFF_E0C, OFF_E1G, OFF_E1C,
                              OFF_D0G, OFF_D0C, OFF_D1G, OFF_D1C};
    const int  Cs[8]   = {130, 130, 256, 256, 130, 130, 256, 256};
    const int  KTBs[8] = {KTB0, KTB0, KTB1, KTB1, KTB0, KTB0, KTB1, KTB1};
    const int  outs[8] = {256, 128, 256, 128, 256, 128, 256, 128};
    for (int i = 0; i < 8; ++i) {
        ws.src[i] = (const float*)d_in[idx[i]];
        ws.off[i] = off[i]; ws.C[i] = Cs[i]; ws.KTB[i] = KTBs[i]; ws.outN[i] = outs[i];
    }
    split_w_kernel<<<dim3(512, 1, 8), 256>>>(ws, wh, wl);
    zero3_kernel<<<gblocks(2LL * NB * HH + NB * DIN, 256), 256>>>(
        h0, (long long)NB * HH, h1, (long long)NB * HH, xdec, (long long)NB * DIN);

    CellW enc0{ wh + OFF_E0G, wl + OFF_E0G, wh + OFF_E0C, wl + OFF_E0C,
                (const float*)d_in[4],  (const float*)d_in[6],
                DIN, CP0, 3, KTB0, f0h, f0l, PSTR0 };
    CellW enc1{ wh + OFF_E1G, wl + OFF_E1G, wh + OFF_E1C, wl + OFF_E1C,
                (const float*)d_in[8],  (const float*)d_in[10],
                HH, CP1, 4, KTB1, f1h, f1l, PSTR1 };
    CellW dec0{ wh + OFF_D0G, wl + OFF_D0G, wh + OFF_D0C, wl + OFF_D0C,
                (const float*)d_in[12], (const float*)d_in[14],
                DIN, CP0, 3, KTB0, f0h, f0l, PSTR0 };
    CellW dec1{ wh + OFF_D1G, wl + OFF_D1G, wh + OFF_D1C, wl + OFF_D1C,
                (const float*)d_in[16], (const float*)d_in[18],
                HH, CP1, 4, KTB1, f1h, f1l, PSTR1 };

    for (int t = 0; t < TT; ++t) {
        run_cell(source, 0, t, h0, enc0);
        run_cell(h0,     1, t, h1, enc1);
    }
    for (int t = 0; t < TT; ++t) {
        run_cell(xdec, 1, t, h0, dec0);
        run_cell(h0,   1, t, h1, dec1);
        dec_proj_kernel<<<(NB + 255) / 256, 256>>>(h1, Wp, bp, out, xdec, t);
    }
}

// round 13
// speedup vs baseline: 1.2288x; 1.2288x over previous
#include <cuda_runtime.h>
#include <cuda_bf16.h>
#include <mma.h>
#include <math.h>
#include <stdint.h>

using namespace nvcuda;

// Problem constants
#define BB  64
#define TT  12
#define NN  325
#define DIN 2
#define HH  128
#define KF  5

#define NB      (NN*BB)          // 20800
#define CP0     144              // padded C for layer0 (130 -> 144)
#define CP1     256              // layer1 C
#define KTB0    192              // weight K rows per plane, layer0 (ceil64(144))
#define KTB1    256

#define PSTR0   (384LL*64*144)   // feats plane stride layer0
#define PSTR1   (384LL*64*256)

// ---------------- static scratch (pads never written => stay zero) ----------
__device__ __align__(256) __nv_bfloat16 g_f0h[5*PSTR0], g_f0l[5*PSTR0];
__device__ __align__(256) __nv_bfloat16 g_f1h[5*PSTR1], g_f1l[5*PSTR1];
__device__ __align__(256) __nv_bfloat16 g_sh[2*384*384], g_sl[2*384*384];
__device__ __align__(256) __nv_bfloat16 g_wh[1720320],   g_wl[1720320];
__device__ float g_gates[(long long)NB*2*HH];
__device__ float g_h0[(long long)NB*HH];
__device__ float g_h1[(long long)NB*HH];
__device__ float g_xdec[(long long)NB*DIN];

static __nv_bfloat16 *g_sh_p = nullptr, *g_sl_p = nullptr;

// weight pool offsets (KF * KTB * out elements each)
#define OFF_E0G 0
#define OFF_E0C 245760
#define OFF_E1G 368640
#define OFF_E1C 696320
#define OFF_D0G 860160
#define OFF_D0C 1105920
#define OFF_D1G 1228800
#define OFF_D1C 1556480

// ---------------------------------------------------------------------------
// helpers / prep
// ---------------------------------------------------------------------------
__device__ __forceinline__ void split2(float v, __nv_bfloat16& hi, __nv_bfloat16& lo) {
    hi = __float2bfloat16_rn(v);
    lo = __float2bfloat16_rn(v - __bfloat162float(hi));
}
__device__ __forceinline__ void cp16(uint32_t s, const void* g) {
    asm volatile("cp.async.cg.shared.global [%0], [%1], 16;\n" :: "r"(s), "l"(g));
}

__global__ void split_sup_kernel(const float* __restrict__ sup) {
    int i = blockIdx.x * blockDim.x + threadIdx.x;
    if (i >= 2 * NN * NN) return;
    int s = i / (NN * NN), r = (i / NN) % NN, c = i % NN;
    __nv_bfloat16 hi, lo; split2(sup[i], hi, lo);
    long long d = (long long)s * 384 * 384 + (long long)r * 384 + c;
    g_sh[d] = hi; g_sl[d] = lo;
}

struct WSpec8 { const float* src[8]; long long off[8]; int C[8], KTB[8], outN[8]; };
__global__ void split_w_kernel(WSpec8 ws, __nv_bfloat16* dh, __nv_bfloat16* dl) {
    int z = blockIdx.z;
    const float* W = ws.src[z];
    int C = ws.C[z], KTB = ws.KTB[z], outN = ws.outN[z];
    long long total = (long long)KF * C * outN;
    for (long long i = blockIdx.x * (long long)blockDim.x + threadIdx.x; i < total;
         i += (long long)gridDim.x * blockDim.x) {
        int p = (int)(i / ((long long)C * outN));
        int rem = (int)(i % ((long long)C * outN));
        int k = rem / outN, o = rem % outN;
        __nv_bfloat16 hi, lo; split2(W[i], hi, lo);
        long long d = ws.off[z] + ((long long)p * KTB + k) * outN + o;
        dh[d] = hi; dl[d] = lo;
    }
}

__global__ void zero3_kernel(float* a, long long na, float* b, long long nb2,
                             float* c, long long nc) {
    long long tot = na + nb2 + nc;
    for (long long i = blockIdx.x * (long long)blockDim.x + threadIdx.x; i < tot;
         i += (long long)gridDim.x * blockDim.x) {
        if (i < na) a[i] = 0.f;
        else if (i < na + nb2) b[i - na] = 0.f;
        else c[i - na - nb2] = 0.f;
    }
}

// ---------------------------------------------------------------------------
// Pipelined bf16-pair GEMM (R4 config: BM=64, BN=128, BK=64, 8 warps 2x4,
// warp tile 32x32, occupancy 2).  C = act( sum_p A_p @ B_p + bias )
// act: 0 = pair out (Ch/Cl), 1 = sigmoid->Cf, 2 = tanh->Cf,
//      3 = tanh + GRU fuse: Cf = z*Cf + (1-z)*tanh(v), z = gIn[gr*256+gc]
// ---------------------------------------------------------------------------
#define SMEM_A_BYTES 36864            // 2 stages * 2(hl) * 64 * 72 * 2B
#define SMEM_B_BYTES 69632            // 2 stages * 2(hl) * 64 * 136 * 2B
#define SMEM_TOTAL   (SMEM_A_BYTES + SMEM_B_BYTES)

__global__ __launch_bounds__(256, 2) void pgemm_kernel(
    int M, int Kt, int ktpp, int nplanes,
    const __nv_bfloat16* __restrict__ Ah, const __nv_bfloat16* __restrict__ Al,
    long long ldaA, long long pstrA, long long aZ,
    const __nv_bfloat16* __restrict__ Bh, const __nv_bfloat16* __restrict__ Bl,
    long long ldbB, long long pstrB, long long bZ,
    float* __restrict__ Cf, __nv_bfloat16* __restrict__ Ch, __nv_bfloat16* __restrict__ Cl,
    long long ldc, long long cZ,
    const float* __restrict__ bias, int act, const float* __restrict__ gIn)
{
    extern __shared__ char smem[];
    __nv_bfloat16* sA = (__nv_bfloat16*)smem;
    __nv_bfloat16* sB = (__nv_bfloat16*)(smem + SMEM_A_BYTES);
    const uint32_t sAu = (uint32_t)__cvta_generic_to_shared(sA);
    const uint32_t sBu = (uint32_t)__cvta_generic_to_shared(sB);

    const int tid = threadIdx.x;
    const int w = tid >> 5, lane = tid & 31;
    const int wm = w >> 2, wn = w & 3;      // 2x4 warps, 32x32 tiles
    const int rowBase = blockIdx.y * 64;
    const int colBase = blockIdx.x * 128;

    Ah += (long long)blockIdx.z * aZ;  Al += (long long)blockIdx.z * aZ;
    Bh += (long long)blockIdx.z * bZ;  Bl += (long long)blockIdx.z * bZ;
    if (Ch) { Ch += (long long)blockIdx.z * cZ; Cl += (long long)blockIdx.z * cZ; }
    if (Cf) { Cf += (long long)blockIdx.z * cZ; }

    auto fill = [&](int stage, int it) {
        int p = it / ktpp;
        int k0 = (it - p * ktpp) * 64;
        const __nv_bfloat16* A0h = Ah + (long long)p * pstrA;
        const __nv_bfloat16* A0l = Al + (long long)p * pstrA;
        const __nv_bfloat16* B0h = Bh + (long long)p * pstrB;
        const __nv_bfloat16* B0l = Bl + (long long)p * pstrB;
#pragma unroll
        for (int t = 0; t < 2; ++t) {                 // A: 512 16B chunks per h/l
            int id = tid + t * 256;
            int row = id >> 3, cc = id & 7;
            int k = k0 + cc * 8;
            uint32_t s0 = sAu + (uint32_t)((((stage * 2 + 0) * 64 + row) * 72 + cc * 8) * 2);
            uint32_t s1 = sAu + (uint32_t)((((stage * 2 + 1) * 64 + row) * 72 + cc * 8) * 2);
            if (k < Kt) {
                long long ga = (long long)(rowBase + row) * ldaA + k;
                cp16(s0, A0h + ga);
                cp16(s1, A0l + ga);
            } else {
                float4 z = {0.f, 0.f, 0.f, 0.f};
                *(float4*)(sA + (((stage * 2 + 0) * 64 + row) * 72 + cc * 8)) = z;
                *(float4*)(sA + (((stage * 2 + 1) * 64 + row) * 72 + cc * 8)) = z;
            }
        }
#pragma unroll
        for (int t = 0; t < 4; ++t) {                 // B: 1024 16B chunks per h/l
            int id = tid + t * 256;
            int row = id >> 4, cc = id & 15;
            long long gb = (long long)(k0 + row) * ldbB + colBase + cc * 8;
            uint32_t s0 = sBu + (uint32_t)((((stage * 2 + 0) * 64 + row) * 136 + cc * 8) * 2);
            uint32_t s1 = sBu + (uint32_t)((((stage * 2 + 1) * 64 + row) * 136 + cc * 8) * 2);
            cp16(s0, B0h + gb);
            cp16(s1, B0l + gb);
        }
        asm volatile("cp.async.commit_group;\n" ::: "memory");
    };

    wmma::fragment<wmma::accumulator, 16, 16, 16, float> acc[2][2];
#pragma unroll
    for (int i = 0; i < 2; ++i)
#pragma unroll
        for (int j = 0; j < 2; ++j) wmma::fill_fragment(acc[i][j], 0.f);

    const int T = ktpp * nplanes;
    fill(0, 0);
    for (int it = 0; it < T; ++it) {
        if (it + 1 < T) {
            fill((it + 1) & 1, it + 1);
            asm volatile("cp.async.wait_group 1;\n" ::: "memory");
        } else {
            asm volatile("cp.async.wait_group 0;\n" ::: "memory");
        }
        __syncthreads();
        const int st = it & 1;
#pragma unroll
        for (int kk = 0; kk < 4; ++kk) {
            wmma::fragment<wmma::matrix_a, 16, 16, 16, __nv_bfloat16, wmma::row_major> a_h[2], a_l[2];
            wmma::fragment<wmma::matrix_b, 16, 16, 16, __nv_bfloat16, wmma::row_major> b_h[2], b_l[2];
#pragma unroll
            for (int i = 0; i < 2; ++i) {
                const int r = wm * 32 + i * 16;
                wmma::load_matrix_sync(a_h[i], sA + ((st * 2 + 0) * 64 + r) * 72 + kk * 16, 72);
                wmma::load_matrix_sync(a_l[i], sA + ((st * 2 + 1) * 64 + r) * 72 + kk * 16, 72);
            }
#pragma unroll
            for (int j = 0; j < 2; ++j) {
                const int c = wn * 32 + j * 16;
                wmma::load_matrix_sync(b_h[j], sB + ((st * 2 + 0) * 64 + kk * 16) * 136 + c, 136);
                wmma::load_matrix_sync(b_l[j], sB + ((st * 2 + 1) * 64 + kk * 16) * 136 + c, 136);
            }
#pragma unroll
            for (int i = 0; i < 2; ++i)
#pragma unroll
                for (int j = 0; j < 2; ++j) {
                    wmma::mma_sync(acc[i][j], a_h[i], b_h[j], acc[i][j]);
                    wmma::mma_sync(acc[i][j], a_h[i], b_l[j], acc[i][j]);
                    wmma::mma_sync(acc[i][j], a_l[i], b_h[j], acc[i][j]);
                }
        }
        __syncthreads();
    }

    // ---- epilogue: warp scratch (reuses sA region: 8 * 32*36 floats) ----
    float* scr = (float*)smem + w * (32 * 36);
#pragma unroll
    for (int i = 0; i < 2; ++i)
#pragma unroll
        for (int j = 0; j < 2; ++j)
            wmma::store_matrix_sync(scr + (i * 16) * 36 + j * 16, acc[i][j], 36,
                                    wmma::mem_row_major);
    __syncwarp();

#pragma unroll
    for (int t = 0; t < 16; ++t) {
        int e = lane + t * 32;
        int r = e >> 4, c = (e & 15) * 2;
        int gr = rowBase + wm * 32 + r;
        if (gr >= M) continue;
        int gc = colBase + wn * 32 + c;
        float v0 = scr[r * 36 + c];
        float v1 = scr[r * 36 + c + 1];
        if (bias) { v0 += bias[gc]; v1 += bias[gc + 1]; }
        if (act == 1) {
            v0 = 1.f / (1.f + expf(-v0)); v1 = 1.f / (1.f + expf(-v1));
        } else if (act == 2) {
            v0 = tanhf(v0); v1 = tanhf(v1);
        } else if (act == 3) {
            v0 = tanhf(v0); v1 = tanhf(v1);
            float z0 = gIn[(long long)gr * (2 * HH) + gc];
            float z1 = gIn[(long long)gr * (2 * HH) + gc + 1];
            long long ho = (long long)gr * ldc + gc;
            v0 = z0 * Cf[ho]     + (1.f - z0) * v0;
            v1 = z1 * Cf[ho + 1] + (1.f - z1) * v1;
        }
        if (Ch) {
            __nv_bfloat16 h0b, l0b, h1b, l1b;
            split2(v0, h0b, l0b); split2(v1, h1b, l1b);
            __nv_bfloat162 hh; hh.x = h0b; hh.y = h1b;
            __nv_bfloat162 ll; ll.x = l0b; ll.y = l1b;
            *(__nv_bfloat162*)&Ch[(long long)gr * ldc + gc] = hh;
            *(__nv_bfloat162*)&Cl[(long long)gr * ldc + gc] = ll;
        } else {
            float2 f; f.x = v0; f.y = v1;
            *(float2*)&Cf[(long long)gr * ldc + gc] = f;
        }
    }
}

// ---------------------------------------------------------------------------
// concat (vectorized): plane 0 of feats (hi/lo) as bf16x2 pairs.
// One thread per 2 consecutive channels. Region boundaries are even, so a
// pair never straddles x/h/pad regions.
// ---------------------------------------------------------------------------
__global__ void concat_kernel(__nv_bfloat16* __restrict__ ph,
                              __nv_bfloat16* __restrict__ pl,
                              const float* __restrict__ xsrc, int xmode, int t,
                              int Cx, int C, int Cp,
                              const float* __restrict__ h,
                              const float* __restrict__ gates, int useR)
{
    const int half = Cp >> 1;
    const int total2 = NB * half;
    int i = blockIdx.x * blockDim.x + threadIdx.x;
    if (i >= total2) return;
    int nb = i / half;
    int c = (i - nb * half) * 2;
    float v0 = 0.f, v1 = 0.f;
    if (c < Cx) {
        if (xmode == 0) {
            int b = nb % BB, n = nb / BB;
            const float2 x2 = *(const float2*)&xsrc[(((long long)b * TT + t) * NN + n) * DIN + c];
            v0 = x2.x; v1 = x2.y;
        } else {
            const float2 x2 = *(const float2*)&h[0];  // placeholder never taken for xmode1 x-region read below
            (void)x2;
            const float2 xx = *(const float2*)&xsrc[(long long)nb * Cx + c];
            v0 = xx.x; v1 = xx.y;
        }
    } else if (c < C) {
        int hc = c - Cx;
        const float2 h2 = *(const float2*)&h[(long long)nb * HH + hc];
        v0 = h2.x; v1 = h2.y;
        if (useR) {
            const float2 r2 = *(const float2*)&gates[(long long)nb * (2 * HH) + HH + hc];
            v0 *= r2.x; v1 *= r2.y;
        }
    }
    __nv_bfloat16 h0b, l0b, h1b, l1b;
    split2(v0, h0b, l0b); split2(v1, h1b, l1b);
    __nv_bfloat162 hh; hh.x = h0b; hh.y = h1b;
    __nv_bfloat162 ll; ll.x = l0b; ll.y = l1b;
    *(__nv_bfloat162*)&ph[(long long)nb * Cp + c] = hh;
    *(__nv_bfloat162*)&pl[(long long)nb * Cp + c] = ll;
}

__global__ void dec_proj_kernel(const float* __restrict__ h1,
                                const float* __restrict__ Wp,
                                const float* __restrict__ bp,
                                float* __restrict__ out,
                                float* __restrict__ xdec, int t)
{
    int row = blockIdx.x * blockDim.x + threadIdx.x;
    if (row >= NB) return;
    int n = row / BB, b = row % BB;
    float a0 = bp[0], a1 = bp[1];
    const float* hr = h1 + (long long)row * HH;
#pragma unroll 8
    for (int k = 0; k < HH; ++k) {
        float hv = hr[k];
        a0 += hv * Wp[k * 2]; a1 += hv * Wp[k * 2 + 1];
    }
    long long o = (((long long)b * TT + t) * NN + n) * 2;
    out[o] = a0; out[o + 1] = a1;
    xdec[(long long)row * 2] = a0; xdec[(long long)row * 2 + 1] = a1;
}

// ---------------------------------------------------------------------------
// host
// ---------------------------------------------------------------------------
static inline int gblocks(long long total, int tpb) {
    long long b = (total + tpb - 1) / tpb;
    if (b > 1048576) b = 1048576;
    return (int)b;
}

struct CellW {
    const __nv_bfloat16 *wgh, *wgl, *wch, *wcl;
    const float *bg, *bc;
    int Cx, Cp, ktpp, KTB;
    __nv_bfloat16 *fh, *fl;
    long long pstr;
};

static float* G_gates;

static void run_cell(const float* xsrc, int xmode, int t, float* h, const CellW& cw)
{
    const int Cp = cw.Cp, C = cw.Cx + HH;
    const int ldN = BB * Cp;
    const long long PS = cw.pstr;
    const long long SUPZ = 384LL * 384;
    const int cgrid = (NB * (Cp >> 1) + 255) / 256;

    dim3 gd(ldN / 128, 6, 2);

    auto diffuse = [&](const __nv_bfloat16* srcH, const __nv_bfloat16* srcL,
                       long long bZ, __nv_bfloat16* dstH, __nv_bfloat16* dstL) {
        pgemm_kernel<<<gd, 256, SMEM_TOTAL>>>(
            NN, 384, 6, 1,
            g_sh_p, g_sl_p, 384, 0, SUPZ,
            srcH, srcL, ldN, 0, bZ,
            nullptr, dstH, dstL, ldN, 2 * PS,
            nullptr, 0, nullptr);
    };

    for (int pass = 0; pass < 2; ++pass) {
        concat_kernel<<<cgrid, 256>>>(cw.fh, cw.fl, xsrc, xmode, t,
                                      cw.Cx, C, Cp, h, G_gates, pass);
        diffuse(cw.fh, cw.fl, 0, cw.fh + PS, cw.fl + PS);
        diffuse(cw.fh + PS, cw.fl + PS, 2 * PS, cw.fh + 2 * PS, cw.fl + 2 * PS);
        if (pass == 0) {
            dim3 g(2, NB / 64, 1);
            pgemm_kernel<<<g, 256, SMEM_TOTAL>>>(
                NB, Cp, cw.ktpp, KF,
                cw.fh, cw.fl, Cp, PS, 0,
                cw.wgh, cw.wgl, 2 * HH, (long long)cw.KTB * 2 * HH, 0,
                G_gates, nullptr, nullptr, 2 * HH, 0,
                cw.bg, 1, nullptr);
        } else {
            dim3 g(1, NB / 64, 1);
            pgemm_kernel<<<g, 256, SMEM_TOTAL>>>(
                NB, Cp, cw.ktpp, KF,
                cw.fh, cw.fl, Cp, PS, 0,
                cw.wch, cw.wcl, HH, (long long)cw.KTB * HH, 0,
                h, nullptr, nullptr, HH, 0,
                cw.bc, 3, G_gates);
        }
    }
}

extern "C" void kernel_launch(void* const* d_in, const int* in_sizes, int n_in,
                              void* d_out, int out_size)
{
    const float* source   = (const float*)d_in[0];
    const float* supports = (const float*)d_in[2];
    const float* Wp = (const float*)d_in[19];
    const float* bp = (const float*)d_in[20];
    float* out = (float*)d_out;

    cudaFuncSetAttribute(pgemm_kernel, cudaFuncAttributeMaxDynamicSharedMemorySize,
                         SMEM_TOTAL);

    __nv_bfloat16 *f0h, *f0l, *f1h, *f1l, *wh, *wl;
    float *h0, *h1, *xdec;
    cudaGetSymbolAddress((void**)&f0h, g_f0h);
    cudaGetSymbolAddress((void**)&f0l, g_f0l);
    cudaGetSymbolAddress((void**)&f1h, g_f1h);
    cudaGetSymbolAddress((void**)&f1l, g_f1l);
    cudaGetSymbolAddress((void**)&g_sh_p, g_sh);
    cudaGetSymbolAddress((void**)&g_sl_p, g_sl);
    cudaGetSymbolAddress((void**)&wh, g_wh);
    cudaGetSymbolAddress((void**)&wl, g_wl);
    cudaGetSymbolAddress((void**)&G_gates, g_gates);
    cudaGetSymbolAddress((void**)&h0, g_h0);
    cudaGetSymbolAddress((void**)&h1, g_h1);
    cudaGetSymbolAddress((void**)&xdec, g_xdec);

    // ---- prep: 3 launches ----
    split_sup_kernel<<<gblocks(2LL * NN * NN, 256), 256>>>(supports);
    WSpec8 ws;
    const int  idx[8]  = {3, 5, 7, 9, 11, 13, 15, 17};
    const long long off[8] = {OFF_E0G, OFF_E0C, OFF_E1G, OFF_E1C,
                              OFF_D0G, OFF_D0C, OFF_D1G, OFF_D1C};
    const int  Cs[8]   = {130, 130, 256, 256, 130, 130, 256, 256};
    const int  KTBs[8] = {KTB0, KTB0, KTB1, KTB1, KTB0, KTB0, KTB1, KTB1};
    const int  outs[8] = {256, 128, 256, 128, 256, 128, 256, 128};
    for (int i = 0; i < 8; ++i) {
        ws.src[i] = (const float*)d_in[idx[i]];
        ws.off[i] = off[i]; ws.C[i] = Cs[i]; ws.KTB[i] = KTBs[i]; ws.outN[i] = outs[i];
    }
    split_w_kernel<<<dim3(512, 1, 8), 256>>>(ws, wh, wl);
    zero3_kernel<<<gblocks(2LL * NB * HH + NB * DIN, 256), 256>>>(
        h0, (long long)NB * HH, h1, (long long)NB * HH, xdec, (long long)NB * DIN);

    CellW enc0{ wh + OFF_E0G, wl + OFF_E0G, wh + OFF_E0C, wl + OFF_E0C,
                (const float*)d_in[4],  (const float*)d_in[6],
                DIN, CP0, 3, KTB0, f0h, f0l, PSTR0 };
    CellW enc1{ wh + OFF_E1G, wl + OFF_E1G, wh + OFF_E1C, wl + OFF_E1C,
                (const float*)d_in[8],  (const float*)d_in[10],
                HH, CP1, 4, KTB1, f1h, f1l, PSTR1 };
    CellW dec0{ wh + OFF_D0G, wl + OFF_D0G, wh + OFF_D0C, wl + OFF_D0C,
                (const float*)d_in[12], (const float*)d_in[14],
                DIN, CP0, 3, KTB0, f0h, f0l, PSTR0 };
    CellW dec1{ wh + OFF_D1G, wl + OFF_D1G, wh + OFF_D1C, wl + OFF_D1C,
                (const float*)d_in[16], (const float*)d_in[18],
                HH, CP1, 4, KTB1, f1h, f1l, PSTR1 };

    for (int t = 0; t < TT; ++t) {
        run_cell(source, 0, t, h0, enc0);
        run_cell(h0,     1, t, h1, enc1);
    }
    for (int t = 0; t < TT; ++t) {
        run_cell(xdec, 1, t, h0, dec0);
        run_cell(h0,   1, t, h1, dec1);
        dec_proj_kernel<<<(NB + 255) / 256, 256>>>(h1, Wp, bp, out, xdec, t);
    }
}

// round 14
// speedup vs baseline: 1.3542x; 1.1020x over previous
#include <cuda_runtime.h>
#include <cuda_bf16.h>
#include <mma.h>
#include <math.h>
#include <stdint.h>

using namespace nvcuda;

// Problem constants
#define BB  64
#define TT  12
#define NN  325
#define DIN 2
#define HH  128
#define KF  5

#define NB      (NN*BB)          // 20800
#define CP0     136              // padded C for layer0 (130 -> 136, 16B rows)
#define CP1     256              // layer1 C
#define KTB0    192              // weight K rows per plane, layer0 (ceil64 cover)
#define KTB1    256

#define PSTR0   (384LL*64*136)   // feats plane stride layer0
#define PSTR1   (384LL*64*256)

// ---------------- static scratch (pads never written => stay zero) ----------
__device__ __align__(256) __nv_bfloat16 g_f0h[5*PSTR0], g_f0l[5*PSTR0];
__device__ __align__(256) __nv_bfloat16 g_f1h[5*PSTR1], g_f1l[5*PSTR1];
__device__ __align__(256) __nv_bfloat16 g_sh[2*384*384], g_sl[2*384*384];
__device__ __align__(256) __nv_bfloat16 g_wh[1720320],   g_wl[1720320];
__device__ float g_gates[(long long)NB*2*HH];
__device__ float g_h0[(long long)NB*HH];
__device__ float g_h1[(long long)NB*HH];
__device__ float g_xdec[(long long)NB*DIN];

static __nv_bfloat16 *g_sh_p = nullptr, *g_sl_p = nullptr;

// weight pool offsets (KF * KTB * out elements each)
#define OFF_E0G 0
#define OFF_E0C 245760
#define OFF_E1G 368640
#define OFF_E1C 696320
#define OFF_D0G 860160
#define OFF_D0C 1105920
#define OFF_D1G 1228800
#define OFF_D1C 1556480

// ---------------------------------------------------------------------------
// helpers / prep
// ---------------------------------------------------------------------------
__device__ __forceinline__ void split2(float v, __nv_bfloat16& hi, __nv_bfloat16& lo) {
    hi = __float2bfloat16_rn(v);
    lo = __float2bfloat16_rn(v - __bfloat162float(hi));
}
__device__ __forceinline__ void cp16(uint32_t s, const void* g) {
    asm volatile("cp.async.cg.shared.global [%0], [%1], 16;\n" :: "r"(s), "l"(g));
}

__global__ void split_sup_kernel(const float* __restrict__ sup) {
    int i = blockIdx.x * blockDim.x + threadIdx.x;
    if (i >= 2 * NN * NN) return;
    int s = i / (NN * NN), r = (i / NN) % NN, c = i % NN;
    __nv_bfloat16 hi, lo; split2(sup[i], hi, lo);
    long long d = (long long)s * 384 * 384 + (long long)r * 384 + c;
    g_sh[d] = hi; g_sl[d] = lo;
}

struct WSpec8 { const float* src[8]; long long off[8]; int C[8], KTB[8], outN[8]; };
__global__ void split_w_kernel(WSpec8 ws, __nv_bfloat16* dh, __nv_bfloat16* dl) {
    int z = blockIdx.z;
    const float* W = ws.src[z];
    int C = ws.C[z], KTB = ws.KTB[z], outN = ws.outN[z];
    long long total = (long long)KF * C * outN;
    for (long long i = blockIdx.x * (long long)blockDim.x + threadIdx.x; i < total;
         i += (long long)gridDim.x * blockDim.x) {
        int p = (int)(i / ((long long)C * outN));
        int rem = (int)(i % ((long long)C * outN));
        int k = rem / outN, o = rem % outN;
        __nv_bfloat16 hi, lo; split2(W[i], hi, lo);
        long long d = ws.off[z] + ((long long)p * KTB + k) * outN + o;
        dh[d] = hi; dl[d] = lo;
    }
}

__global__ void zero3_kernel(float* a, long long na, float* b, long long nb2,
                             float* c, long long nc) {
    long long tot = na + nb2 + nc;
    for (long long i = blockIdx.x * (long long)blockDim.x + threadIdx.x; i < tot;
         i += (long long)gridDim.x * blockDim.x) {
        if (i < na) a[i] = 0.f;
        else if (i < na + nb2) b[i - na] = 0.f;
        else c[i - na - nb2] = 0.f;
    }
}

// ---------------------------------------------------------------------------
// Pipelined bf16-pair GEMM (BM=64, BN=128, BK=64, 8 warps 2x4, occupancy 2).
//   C = act( sum_p A_p @ B_p + bias )
// Column tiles: colBase = (blockIdx.x * colMul + colAdd) * 128  — lets a
// launch cover only the h-column tiles (colMul=2, colAdd=1) for the
// candidate-pass diffusion of layer-1 cells.
// act: 0 = pair out (Ch/Cl), 1 = sigmoid->Cf, 2 = tanh->Cf,
//      3 = tanh + GRU fuse: Cf = z*Cf + (1-z)*tanh(v), z = gIn[gr*256+gc]
// ---------------------------------------------------------------------------
#define SMEM_A_BYTES 36864            // 2 stages * 2(hl) * 64 * 72 * 2B
#define SMEM_B_BYTES 69632            // 2 stages * 2(hl) * 64 * 136 * 2B
#define SMEM_TOTAL   (SMEM_A_BYTES + SMEM_B_BYTES)

__global__ __launch_bounds__(256, 2) void pgemm_kernel(
    int M, int Kt, int ktpp, int nplanes,
    const __nv_bfloat16* __restrict__ Ah, const __nv_bfloat16* __restrict__ Al,
    long long ldaA, long long pstrA, long long aZ,
    const __nv_bfloat16* __restrict__ Bh, const __nv_bfloat16* __restrict__ Bl,
    long long ldbB, long long pstrB, long long bZ,
    float* __restrict__ Cf, __nv_bfloat16* __restrict__ Ch, __nv_bfloat16* __restrict__ Cl,
    long long ldc, long long cZ,
    const float* __restrict__ bias, int act, const float* __restrict__ gIn,
    int colMul, int colAdd)
{
    extern __shared__ char smem[];
    __nv_bfloat16* sA = (__nv_bfloat16*)smem;
    __nv_bfloat16* sB = (__nv_bfloat16*)(smem + SMEM_A_BYTES);
    const uint32_t sAu = (uint32_t)__cvta_generic_to_shared(sA);
    const uint32_t sBu = (uint32_t)__cvta_generic_to_shared(sB);

    const int tid = threadIdx.x;
    const int w = tid >> 5, lane = tid & 31;
    const int wm = w >> 2, wn = w & 3;      // 2x4 warps, 32x32 tiles
    const int rowBase = blockIdx.y * 64;
    const int colBase = (blockIdx.x * colMul + colAdd) * 128;

    Ah += (long long)blockIdx.z * aZ;  Al += (long long)blockIdx.z * aZ;
    Bh += (long long)blockIdx.z * bZ;  Bl += (long long)blockIdx.z * bZ;
    if (Ch) { Ch += (long long)blockIdx.z * cZ; Cl += (long long)blockIdx.z * cZ; }
    if (Cf) { Cf += (long long)blockIdx.z * cZ; }

    auto fill = [&](int stage, int it) {
        int p = it / ktpp;
        int k0 = (it - p * ktpp) * 64;
        const __nv_bfloat16* A0h = Ah + (long long)p * pstrA;
        const __nv_bfloat16* A0l = Al + (long long)p * pstrA;
        const __nv_bfloat16* B0h = Bh + (long long)p * pstrB;
        const __nv_bfloat16* B0l = Bl + (long long)p * pstrB;
#pragma unroll
        for (int t = 0; t < 2; ++t) {                 // A: 512 16B chunks per h/l
            int id = tid + t * 256;
            int row = id >> 3, cc = id & 7;
            int k = k0 + cc * 8;
            uint32_t s0 = sAu + (uint32_t)((((stage * 2 + 0) * 64 + row) * 72 + cc * 8) * 2);
            uint32_t s1 = sAu + (uint32_t)((((stage * 2 + 1) * 64 + row) * 72 + cc * 8) * 2);
            if (k < Kt) {
                long long ga = (long long)(rowBase + row) * ldaA + k;
                cp16(s0, A0h + ga);
                cp16(s1, A0l + ga);
            } else {
                float4 z = {0.f, 0.f, 0.f, 0.f};
                *(float4*)(sA + (((stage * 2 + 0) * 64 + row) * 72 + cc * 8)) = z;
                *(float4*)(sA + (((stage * 2 + 1) * 64 + row) * 72 + cc * 8)) = z;
            }
        }
#pragma unroll
        for (int t = 0; t < 4; ++t) {                 // B: 1024 16B chunks per h/l
            int id = tid + t * 256;
            int row = id >> 4, cc = id & 15;
            long long gb = (long long)(k0 + row) * ldbB + colBase + cc * 8;
            uint32_t s0 = sBu + (uint32_t)((((stage * 2 + 0) * 64 + row) * 136 + cc * 8) * 2);
            uint32_t s1 = sBu + (uint32_t)((((stage * 2 + 1) * 64 + row) * 136 + cc * 8) * 2);
            cp16(s0, B0h + gb);
            cp16(s1, B0l + gb);
        }
        asm volatile("cp.async.commit_group;\n" ::: "memory");
    };

    wmma::fragment<wmma::accumulator, 16, 16, 16, float> acc[2][2];
#pragma unroll
    for (int i = 0; i < 2; ++i)
#pragma unroll
        for (int j = 0; j < 2; ++j) wmma::fill_fragment(acc[i][j], 0.f);

    const int T = ktpp * nplanes;
    fill(0, 0);
    for (int it = 0; it < T; ++it) {
        if (it + 1 < T) {
            fill((it + 1) & 1, it + 1);
            asm volatile("cp.async.wait_group 1;\n" ::: "memory");
        } else {
            asm volatile("cp.async.wait_group 0;\n" ::: "memory");
        }
        __syncthreads();
        const int st = it & 1;
#pragma unroll
        for (int kk = 0; kk < 4; ++kk) {
            wmma::fragment<wmma::matrix_a, 16, 16, 16, __nv_bfloat16, wmma::row_major> a_h[2], a_l[2];
            wmma::fragment<wmma::matrix_b, 16, 16, 16, __nv_bfloat16, wmma::row_major> b_h[2], b_l[2];
#pragma unroll
            for (int i = 0; i < 2; ++i) {
                const int r = wm * 32 + i * 16;
                wmma::load_matrix_sync(a_h[i], sA + ((st * 2 + 0) * 64 + r) * 72 + kk * 16, 72);
                wmma::load_matrix_sync(a_l[i], sA + ((st * 2 + 1) * 64 + r) * 72 + kk * 16, 72);
            }
#pragma unroll
            for (int j = 0; j < 2; ++j) {
                const int c = wn * 32 + j * 16;
                wmma::load_matrix_sync(b_h[j], sB + ((st * 2 + 0) * 64 + kk * 16) * 136 + c, 136);
                wmma::load_matrix_sync(b_l[j], sB + ((st * 2 + 1) * 64 + kk * 16) * 136 + c, 136);
            }
#pragma unroll
            for (int i = 0; i < 2; ++i)
#pragma unroll
                for (int j = 0; j < 2; ++j) {
                    wmma::mma_sync(acc[i][j], a_h[i], b_h[j], acc[i][j]);
                    wmma::mma_sync(acc[i][j], a_h[i], b_l[j], acc[i][j]);
                    wmma::mma_sync(acc[i][j], a_l[i], b_h[j], acc[i][j]);
                }
        }
        __syncthreads();
    }

    // ---- epilogue: warp scratch (reuses sA region: 8 * 32*36 floats) ----
    float* scr = (float*)smem + w * (32 * 36);
#pragma unroll
    for (int i = 0; i < 2; ++i)
#pragma unroll
        for (int j = 0; j < 2; ++j)
            wmma::store_matrix_sync(scr + (i * 16) * 36 + j * 16, acc[i][j], 36,
                                    wmma::mem_row_major);
    __syncwarp();

#pragma unroll
    for (int t = 0; t < 16; ++t) {
        int e = lane + t * 32;
        int r = e >> 4, c = (e & 15) * 2;
        int gr = rowBase + wm * 32 + r;
        if (gr >= M) continue;
        int gc = colBase + wn * 32 + c;
        float v0 = scr[r * 36 + c];
        float v1 = scr[r * 36 + c + 1];
        if (bias) { v0 += bias[gc]; v1 += bias[gc + 1]; }
        if (act == 1) {
            v0 = 1.f / (1.f + expf(-v0)); v1 = 1.f / (1.f + expf(-v1));
        } else if (act == 2) {
            v0 = tanhf(v0); v1 = tanhf(v1);
        } else if (act == 3) {
            v0 = tanhf(v0); v1 = tanhf(v1);
            float z0 = gIn[(long long)gr * (2 * HH) + gc];
            float z1 = gIn[(long long)gr * (2 * HH) + gc + 1];
            long long ho = (long long)gr * ldc + gc;
            v0 = z0 * Cf[ho]     + (1.f - z0) * v0;
            v1 = z1 * Cf[ho + 1] + (1.f - z1) * v1;
        }
        if (Ch) {
            __nv_bfloat16 h0b, l0b, h1b, l1b;
            split2(v0, h0b, l0b); split2(v1, h1b, l1b);
            __nv_bfloat162 hh; hh.x = h0b; hh.y = h1b;
            __nv_bfloat162 ll; ll.x = l0b; ll.y = l1b;
            *(__nv_bfloat162*)&Ch[(long long)gr * ldc + gc] = hh;
            *(__nv_bfloat162*)&Cl[(long long)gr * ldc + gc] = ll;
        } else {
            float2 f; f.x = v0; f.y = v1;
            *(float2*)&Cf[(long long)gr * ldc + gc] = f;
        }
    }
}

// ---------------------------------------------------------------------------
// concat (vectorized, channel range [cBeg, Cp)): plane 0 of feats (hi/lo).
// cBeg=0 for full build; cBeg=Cx for candidate-pass h-only rewrite (layer 1).
// Region boundaries are even, so a bf16x2 pair never straddles regions.
// ---------------------------------------------------------------------------
__global__ void concat_kernel(__nv_bfloat16* __restrict__ ph,
                              __nv_bfloat16* __restrict__ pl,
                              const float* __restrict__ xsrc, int xmode, int t,
                              int Cx, int C, int Cp, int cBeg,
                              const float* __restrict__ h,
                              const float* __restrict__ gates, int useR)
{
    const int half = (Cp - cBeg) >> 1;
    const int total2 = NB * half;
    int i = blockIdx.x * blockDim.x + threadIdx.x;
    if (i >= total2) return;
    int nb = i / half;
    int c = cBeg + (i - nb * half) * 2;
    float v0 = 0.f, v1 = 0.f;
    if (c < Cx) {
        if (xmode == 0) {
            int b = nb % BB, n = nb / BB;
            const float2 x2 = *(const float2*)&xsrc[(((long long)b * TT + t) * NN + n) * DIN + c];
            v0 = x2.x; v1 = x2.y;
        } else {
            const float2 x2 = *(const float2*)&xsrc[(long long)nb * Cx + c];
            v0 = x2.x; v1 = x2.y;
        }
    } else if (c < C) {
        int hc = c - Cx;
        const float2 h2 = *(const float2*)&h[(long long)nb * HH + hc];
        v0 = h2.x; v1 = h2.y;
        if (useR) {
            const float2 r2 = *(const float2*)&gates[(long long)nb * (2 * HH) + HH + hc];
            v0 *= r2.x; v1 *= r2.y;
        }
    }
    __nv_bfloat16 h0b, l0b, h1b, l1b;
    split2(v0, h0b, l0b); split2(v1, h1b, l1b);
    __nv_bfloat162 hh; hh.x = h0b; hh.y = h1b;
    __nv_bfloat162 ll; ll.x = l0b; ll.y = l1b;
    *(__nv_bfloat162*)&ph[(long long)nb * Cp + c] = hh;
    *(__nv_bfloat162*)&pl[(long long)nb * Cp + c] = ll;
}

__global__ void dec_proj_kernel(const float* __restrict__ h1,
                                const float* __restrict__ Wp,
                                const float* __restrict__ bp,
                                float* __restrict__ out,
                                float* __restrict__ xdec, int t)
{
    int row = blockIdx.x * blockDim.x + threadIdx.x;
    if (row >= NB) return;
    int n = row / BB, b = row % BB;
    float a0 = bp[0], a1 = bp[1];
    const float* hr = h1 + (long long)row * HH;
#pragma unroll 8
    for (int k = 0; k < HH; ++k) {
        float hv = hr[k];
        a0 += hv * Wp[k * 2]; a1 += hv * Wp[k * 2 + 1];
    }
    long long o = (((long long)b * TT + t) * NN + n) * 2;
    out[o] = a0; out[o + 1] = a1;
    xdec[(long long)row * 2] = a0; xdec[(long long)row * 2 + 1] = a1;
}

// ---------------------------------------------------------------------------
// host
// ---------------------------------------------------------------------------
static inline int gblocks(long long total, int tpb) {
    long long b = (total + tpb - 1) / tpb;
    if (b > 1048576) b = 1048576;
    return (int)b;
}

struct CellW {
    const __nv_bfloat16 *wgh, *wgl, *wch, *wcl;
    const float *bg, *bc;
    int Cx, Cp, ktpp, KTB, hOnly;     // hOnly: x-tiles/h-tiles alternate (layer1)
    __nv_bfloat16 *fh, *fl;
    long long pstr;
};

static float* G_gates;

static void run_cell(const float* xsrc, int xmode, int t, float* h, const CellW& cw)
{
    const int Cp = cw.Cp, C = cw.Cx + HH;
    const int ldN = BB * Cp;
    const long long PS = cw.pstr;
    const long long SUPZ = 384LL * 384;

    auto diffuse = [&](const __nv_bfloat16* srcH, const __nv_bfloat16* srcL,
                       long long bZ, __nv_bfloat16* dstH, __nv_bfloat16* dstL,
                       int hOnlyPass) {
        int cm = hOnlyPass ? 2 : 1, ca = hOnlyPass ? 1 : 0;
        dim3 gd(ldN / (128 * cm), 6, 2);
        pgemm_kernel<<<gd, 256, SMEM_TOTAL>>>(
            NN, 384, 6, 1,
            g_sh_p, g_sl_p, 384, 0, SUPZ,
            srcH, srcL, ldN, 0, bZ,
            nullptr, dstH, dstL, ldN, 2 * PS,
            nullptr, 0, nullptr, cm, ca);
    };

    for (int pass = 0; pass < 2; ++pass) {
        const int ho = (pass == 1 && cw.hOnly) ? 1 : 0;
        const int cBeg = ho ? cw.Cx : 0;
        const int cgrid = (NB * ((Cp - cBeg) >> 1) + 255) / 256;
        concat_kernel<<<cgrid, 256>>>(cw.fh, cw.fl, xsrc, xmode, t,
                                      cw.Cx, C, Cp, cBeg, h, G_gates, pass);
        diffuse(cw.fh, cw.fl, 0, cw.fh + PS, cw.fl + PS, ho);
        diffuse(cw.fh + PS, cw.fl + PS, 2 * PS, cw.fh + 2 * PS, cw.fl + 2 * PS, ho);
        if (pass == 0) {
            dim3 g(2, NB / 64, 1);
            pgemm_kernel<<<g, 256, SMEM_TOTAL>>>(
                NB, Cp, cw.ktpp, KF,
                cw.fh, cw.fl, Cp, PS, 0,
                cw.wgh, cw.wgl, 2 * HH, (long long)cw.KTB * 2 * HH, 0,
                G_gates, nullptr, nullptr, 2 * HH, 0,
                cw.bg, 1, nullptr, 1, 0);
        } else {
            dim3 g(1, NB / 64, 1);
            pgemm_kernel<<<g, 256, SMEM_TOTAL>>>(
                NB, Cp, cw.ktpp, KF,
                cw.fh, cw.fl, Cp, PS, 0,
                cw.wch, cw.wcl, HH, (long long)cw.KTB * HH, 0,
                h, nullptr, nullptr, HH, 0,
                cw.bc, 3, G_gates, 1, 0);
        }
    }
}

extern "C" void kernel_launch(void* const* d_in, const int* in_sizes, int n_in,
                              void* d_out, int out_size)
{
    const float* source   = (const float*)d_in[0];
    const float* supports = (const float*)d_in[2];
    const float* Wp = (const float*)d_in[19];
    const float* bp = (const float*)d_in[20];
    float* out = (float*)d_out;

    cudaFuncSetAttribute(pgemm_kernel, cudaFuncAttributeMaxDynamicSharedMemorySize,
                         SMEM_TOTAL);

    __nv_bfloat16 *f0h, *f0l, *f1h, *f1l, *wh, *wl;
    float *h0, *h1, *xdec;
    cudaGetSymbolAddress((void**)&f0h, g_f0h);
    cudaGetSymbolAddress((void**)&f0l, g_f0l);
    cudaGetSymbolAddress((void**)&f1h, g_f1h);
    cudaGetSymbolAddress((void**)&f1l, g_f1l);
    cudaGetSymbolAddress((void**)&g_sh_p, g_sh);
    cudaGetSymbolAddress((void**)&g_sl_p, g_sl);
    cudaGetSymbolAddress((void**)&wh, g_wh);
    cudaGetSymbolAddress((void**)&wl, g_wl);
    cudaGetSymbolAddress((void**)&G_gates, g_gates);
    cudaGetSymbolAddress((void**)&h0, g_h0);
    cudaGetSymbolAddress((void**)&h1, g_h1);
    cudaGetSymbolAddress((void**)&xdec, g_xdec);

    // ---- prep: 3 launches ----
    split_sup_kernel<<<gblocks(2LL * NN * NN, 256), 256>>>(supports);
    WSpec8 ws;
    const int  idx[8]  = {3, 5, 7, 9, 11, 13, 15, 17};
    const long long off[8] = {OFF_E0G, OFF_E0C, OFF_E1G, OFF_E1C,
                              OFF_D0G, OFF_D0C, OFF_D1G, OFF_D1C};
    const int  Cs[8]   = {130, 130, 256, 256, 130, 130, 256, 256};
    const int  KTBs[8] = {KTB0, KTB0, KTB1, KTB1, KTB0, KTB0, KTB1, KTB1};
    const int  outs[8] = {256, 128, 256, 128, 256, 128, 256, 128};
    for (int i = 0; i < 8; ++i) {
        ws.src[i] = (const float*)d_in[idx[i]];
        ws.off[i] = off[i]; ws.C[i] = Cs[i]; ws.KTB[i] = KTBs[i]; ws.outN[i] = outs[i];
    }
    split_w_kernel<<<dim3(512, 1, 8), 256>>>(ws, wh, wl);
    zero3_kernel<<<gblocks(2LL * NB * HH + NB * DIN, 256), 256>>>(
        h0, (long long)NB * HH, h1, (long long)NB * HH, xdec, (long long)NB * DIN);

    CellW enc0{ wh + OFF_E0G, wl + OFF_E0G, wh + OFF_E0C, wl + OFF_E0C,
                (const float*)d_in[4],  (const float*)d_in[6],
                DIN, CP0, 3, KTB0, 0, f0h, f0l, PSTR0 };
    CellW enc1{ wh + OFF_E1G, wl + OFF_E1G, wh + OFF_E1C, wl + OFF_E1C,
                (const float*)d_in[8],  (const float*)d_in[10],
                HH, CP1, 4, KTB1, 1, f1h, f1l, PSTR1 };
    CellW dec0{ wh + OFF_D0G, wl + OFF_D0G, wh + OFF_D0C, wl + OFF_D0C,
                (const float*)d_in[12], (const float*)d_in[14],
                DIN, CP0, 3, KTB0, 0, f0h, f0l, PSTR0 };
    CellW dec1{ wh + OFF_D1G, wl + OFF_D1G, wh + OFF_D1C, wl + OFF_D1C,
                (const float*)d_in[16], (const float*)d_in[18],
                HH, CP1, 4, KTB1, 1, f1h, f1l, PSTR1 };

    for (int t = 0; t < TT; ++t) {
        run_cell(source, 0, t, h0, enc0);
        run_cell(h0,     1, t, h1, enc1);
    }
    for (int t = 0; t < TT; ++t) {
        run_cell(xdec, 1, t, h0, dec0);
        run_cell(h0,   1, t, h1, dec1);
        dec_proj_kernel<<<(NB + 255) / 256, 256>>>(h1, Wp, bp, out, xdec, t);
    }
}

// round 16
// speedup vs baseline: 1.4024x; 1.0357x over previous
#include <cuda_runtime.h>
#include <cuda_bf16.h>
#include <mma.h>
#include <math.h>
#include <stdint.h>

using namespace nvcuda;

// Problem constants
#define BB  64
#define TT  12
#define NN  325
#define DIN 2
#define HH  128
#define KF  5

#define NB      (NN*BB)          // 20800
#define CP0     136              // padded C for layer0 (130 -> 136, 16B rows)
#define CP1     256              // layer1 C

#define PSTR0   (384LL*64*136)   // feats plane stride layer0
#define PSTR1   (384LL*64*256)

// dense-packed weight K extents (5 planes x Cp), covered to 64-chunks
#define KD0     680              // 5*136
#define KD0C    704              // ceil64
#define KD1     1280             // 5*256 (already 64-multiple)

// ---------------- static scratch (pads never written => stay zero) ----------
__device__ __align__(256) __nv_bfloat16 g_f0h[5*PSTR0], g_f0l[5*PSTR0];
__device__ __align__(256) __nv_bfloat16 g_f1h[5*PSTR1], g_f1l[5*PSTR1];
__device__ __align__(256) __nv_bfloat16 g_sh[2*384*384], g_sl[2*384*384];
__device__ __align__(256) __nv_bfloat16 g_wh[1523712],   g_wl[1523712];
__device__ float g_gates[(long long)NB*2*HH];
__device__ float g_h0[(long long)NB*HH];
__device__ float g_h1[(long long)NB*HH];
__device__ float g_xdec[(long long)NB*DIN];

static __nv_bfloat16 *g_sh_p = nullptr, *g_sl_p = nullptr;

// weight pool offsets (dense pack, tail rows zero)
#define OFF_E0G 0         // 704*256 = 180224
#define OFF_E0C 180224    // 704*128 =  90112
#define OFF_E1G 270336    // 1280*256 = 327680
#define OFF_E1C 598016    // 1280*128 = 163840
#define OFF_D0G 761856
#define OFF_D0C 942080
#define OFF_D1G 1032192
#define OFF_D1C 1359872

// ---------------------------------------------------------------------------
// helpers / prep
// ---------------------------------------------------------------------------
__device__ __forceinline__ void split2(float v, __nv_bfloat16& hi, __nv_bfloat16& lo) {
    hi = __float2bfloat16_rn(v);
    lo = __float2bfloat16_rn(v - __bfloat162float(hi));
}
__device__ __forceinline__ void cp16(uint32_t s, const void* g) {
    asm volatile("cp.async.cg.shared.global [%0], [%1], 16;\n" :: "r"(s), "l"(g));
}

__global__ void split_sup_kernel(const float* __restrict__ sup) {
    int i = blockIdx.x * blockDim.x + threadIdx.x;
    if (i >= 2 * NN * NN) return;
    int s = i / (NN * NN), r = (i / NN) % NN, c = i % NN;
    __nv_bfloat16 hi, lo; split2(sup[i], hi, lo);
    long long d = (long long)s * 384 * 384 + (long long)r * 384 + c;
    g_sh[d] = hi; g_sl[d] = lo;
}

struct WSpec8 { const float* src[8]; long long off[8]; int C[8], Cp[8], outN[8]; };
__global__ void split_w_kernel(WSpec8 ws, __nv_bfloat16* dh, __nv_bfloat16* dl) {
    int z = blockIdx.z;
    const float* W = ws.src[z];
    int C = ws.C[z], Cp = ws.Cp[z], outN = ws.outN[z];
    long long total = (long long)KF * C * outN;
    for (long long i = blockIdx.x * (long long)blockDim.x + threadIdx.x; i < total;
         i += (long long)gridDim.x * blockDim.x) {
        int p = (int)(i / ((long long)C * outN));
        int rem = (int)(i % ((long long)C * outN));
        int k = rem / outN, o = rem % outN;
        __nv_bfloat16 hi, lo; split2(W[i], hi, lo);
        long long d = ws.off[z] + ((long long)p * Cp + k) * outN + o;
        dh[d] = hi; dl[d] = lo;
    }
}

__global__ void zero3_kernel(float* a, long long na, float* b, long long nb2,
                             float* c, long long nc) {
    long long tot = na + nb2 + nc;
    for (long long i = blockIdx.x * (long long)blockDim.x + threadIdx.x; i < tot;
         i += (long long)gridDim.x * blockDim.x) {
        if (i < na) a[i] = 0.f;
        else if (i < na + nb2) b[i - na] = 0.f;
        else c[i - na - nb2] = 0.f;
    }
}

// ---------------------------------------------------------------------------
// Pipelined bf16-pair GEMM (BM=64, BN=128, BK=64, 8 warps 2x4, occupancy 2).
//   C = act( A @ B + bias ),  A planar: global k -> (plane, kk) via cpp
//   (cpp = 16B-chunks per A plane; a 16B chunk never straddles planes).
// B is dense [Kcover x N].  Kt guards the A tail (zero-filled).
// colBase = (blockIdx.x * colMul + colAdd) * 128  (h-only diffusion tiles).
// act: 0 = pair out (Ch/Cl), 1 = sigmoid->Cf, 2 = tanh->Cf,
//      3 = tanh + GRU fuse: Cf = z*Cf + (1-z)*tanh(v), z = gIn[gr*256+gc]
// ---------------------------------------------------------------------------
#define SMEM_A_BYTES 36864            // 2 stages * 2(hl) * 64 * 72 * 2B
#define SMEM_B_BYTES 69632            // 2 stages * 2(hl) * 64 * 136 * 2B
#define SMEM_TOTAL   (SMEM_A_BYTES + SMEM_B_BYTES)

__global__ __launch_bounds__(256, 2) void pgemm_kernel(
    int M, int T, int Kt, int cpp,
    const __nv_bfloat16* __restrict__ Ah, const __nv_bfloat16* __restrict__ Al,
    long long ldaA, long long pstrA, long long aZ,
    const __nv_bfloat16* __restrict__ Bh, const __nv_bfloat16* __restrict__ Bl,
    long long ldbB, long long bZ,
    float* __restrict__ Cf, __nv_bfloat16* __restrict__ Ch, __nv_bfloat16* __restrict__ Cl,
    long long ldc, long long cZ,
    const float* __restrict__ bias, int act, const float* __restrict__ gIn,
    int colMul, int colAdd)
{
    extern __shared__ char smem[];
    __nv_bfloat16* sA = (__nv_bfloat16*)smem;
    __nv_bfloat16* sB = (__nv_bfloat16*)(smem + SMEM_A_BYTES);
    const uint32_t sAu = (uint32_t)__cvta_generic_to_shared(sA);
    const uint32_t sBu = (uint32_t)__cvta_generic_to_shared(sB);

    const int tid = threadIdx.x;
    const int w = tid >> 5, lane = tid & 31;
    const int wm = w >> 2, wn = w & 3;      // 2x4 warps, 32x32 tiles
    const int rowBase = blockIdx.y * 64;
    const int colBase = (blockIdx.x * colMul + colAdd) * 128;

    Ah += (long long)blockIdx.z * aZ;  Al += (long long)blockIdx.z * aZ;
    Bh += (long long)blockIdx.z * bZ;  Bl += (long long)blockIdx.z * bZ;
    if (Ch) { Ch += (long long)blockIdx.z * cZ; Cl += (long long)blockIdx.z * cZ; }
    if (Cf) { Cf += (long long)blockIdx.z * cZ; }

    auto fill = [&](int stage, int it) {
        const int k0 = it * 64;
#pragma unroll
        for (int t = 0; t < 2; ++t) {                 // A: 512 16B chunks per h/l
            int id = tid + t * 256;
            int row = id >> 3, cc = id & 7;
            int gk = k0 + cc * 8;
            uint32_t s0 = sAu + (uint32_t)((((stage * 2 + 0) * 64 + row) * 72 + cc * 8) * 2);
            uint32_t s1 = sAu + (uint32_t)((((stage * 2 + 1) * 64 + row) * 72 + cc * 8) * 2);
            if (gk < Kt) {
                int chunk = gk >> 3;
                int p = chunk / cpp;
                int kk = chunk - p * cpp;
                long long ga = (long long)p * pstrA + (long long)(rowBase + row) * ldaA + kk * 8;
                cp16(s0, Ah + ga);
                cp16(s1, Al + ga);
            } else {
                float4 z = {0.f, 0.f, 0.f, 0.f};
                *(float4*)(sA + (((stage * 2 + 0) * 64 + row) * 72 + cc * 8)) = z;
                *(float4*)(sA + (((stage * 2 + 1) * 64 + row) * 72 + cc * 8)) = z;
            }
        }
#pragma unroll
        for (int t = 0; t < 4; ++t) {                 // B: 1024 16B chunks per h/l
            int id = tid + t * 256;
            int row = id >> 4, cc = id & 15;
            long long gb = (long long)(k0 + row) * ldbB + colBase + cc * 8;
            uint32_t s0 = sBu + (uint32_t)((((stage * 2 + 0) * 64 + row) * 136 + cc * 8) * 2);
            uint32_t s1 = sBu + (uint32_t)((((stage * 2 + 1) * 64 + row) * 136 + cc * 8) * 2);
            cp16(s0, Bh + gb);
            cp16(s1, Bl + gb);
        }
        asm volatile("cp.async.commit_group;\n" ::: "memory");
    };

    wmma::fragment<wmma::accumulator, 16, 16, 16, float> acc[2][2];
#pragma unroll
    for (int i = 0; i < 2; ++i)
#pragma unroll
        for (int j = 0; j < 2; ++j) wmma::fill_fragment(acc[i][j], 0.f);

    fill(0, 0);
    for (int it = 0; it < T; ++it) {
        if (it + 1 < T) {
            fill((it + 1) & 1, it + 1);
            asm volatile("cp.async.wait_group 1;\n" ::: "memory");
        } else {
            asm volatile("cp.async.wait_group 0;\n" ::: "memory");
        }
        __syncthreads();
        const int st = it & 1;
#pragma unroll
        for (int kk = 0; kk < 4; ++kk) {
            wmma::fragment<wmma::matrix_a, 16, 16, 16, __nv_bfloat16, wmma::row_major> a_h[2], a_l[2];
            wmma::fragment<wmma::matrix_b, 16, 16, 16, __nv_bfloat16, wmma::row_major> b_h[2], b_l[2];
#pragma unroll
            for (int i = 0; i < 2; ++i) {
                const int r = wm * 32 + i * 16;
                wmma::load_matrix_sync(a_h[i], sA + ((st * 2 + 0) * 64 + r) * 72 + kk * 16, 72);
                wmma::load_matrix_sync(a_l[i], sA + ((st * 2 + 1) * 64 + r) * 72 + kk * 16, 72);
            }
#pragma unroll
            for (int j = 0; j < 2; ++j) {
                const int c = wn * 32 + j * 16;
                wmma::load_matrix_sync(b_h[j], sB + ((st * 2 + 0) * 64 + kk * 16) * 136 + c, 136);
                wmma::load_matrix_sync(b_l[j], sB + ((st * 2 + 1) * 64 + kk * 16) * 136 + c, 136);
            }
#pragma unroll
            for (int i = 0; i < 2; ++i)
#pragma unroll
                for (int j = 0; j < 2; ++j) {
                    wmma::mma_sync(acc[i][j], a_h[i], b_h[j], acc[i][j]);
                    wmma::mma_sync(acc[i][j], a_h[i], b_l[j], acc[i][j]);
                    wmma::mma_sync(acc[i][j], a_l[i], b_h[j], acc[i][j]);
                }
        }
        __syncthreads();
    }

    // ---- epilogue: warp scratch (reuses sA region: 8 * 32*36 floats) ----
    float* scr = (float*)smem + w * (32 * 36);
#pragma unroll
    for (int i = 0; i < 2; ++i)
#pragma unroll
        for (int j = 0; j < 2; ++j)
            wmma::store_matrix_sync(scr + (i * 16) * 36 + j * 16, acc[i][j], 36,
                                    wmma::mem_row_major);
    __syncwarp();

#pragma unroll
    for (int t = 0; t < 16; ++t) {
        int e = lane + t * 32;
        int r = e >> 4, c = (e & 15) * 2;
        int gr = rowBase + wm * 32 + r;
        if (gr >= M) continue;
        int gc = colBase + wn * 32 + c;
        float v0 = scr[r * 36 + c];
        float v1 = scr[r * 36 + c + 1];
        if (bias) { v0 += bias[gc]; v1 += bias[gc + 1]; }
        if (act == 1) {
            v0 = 1.f / (1.f + expf(-v0)); v1 = 1.f / (1.f + expf(-v1));
        } else if (act == 2) {
            v0 = tanhf(v0); v1 = tanhf(v1);
        } else if (act == 3) {
            v0 = tanhf(v0); v1 = tanhf(v1);
            float z0 = gIn[(long long)gr * (2 * HH) + gc];
            float z1 = gIn[(long long)gr * (2 * HH) + gc + 1];
            long long ho = (long long)gr * ldc + gc;
            v0 = z0 * Cf[ho]     + (1.f - z0) * v0;
            v1 = z1 * Cf[ho + 1] + (1.f - z1) * v1;
        }
        if (Ch) {
            __nv_bfloat16 h0b, l0b, h1b, l1b;
            split2(v0, h0b, l0b); split2(v1, h1b, l1b);
            __nv_bfloat162 hh; hh.x = h0b; hh.y = h1b;
            __nv_bfloat162 ll; ll.x = l0b; ll.y = l1b;
            *(__nv_bfloat162*)&Ch[(long long)gr * ldc + gc] = hh;
            *(__nv_bfloat162*)&Cl[(long long)gr * ldc + gc] = ll;
        } else {
            float2 f; f.x = v0; f.y = v1;
            *(float2*)&Cf[(long long)gr * ldc + gc] = f;
        }
    }
}

// ---------------------------------------------------------------------------
// concat (vectorized, channel range [cBeg, Cp)): plane 0 of feats (hi/lo).
// cBeg=0 for full build; cBeg=Cx for candidate-pass h-only rewrite (layer 1).
// ---------------------------------------------------------------------------
__global__ void concat_kernel(__nv_bfloat16* __restrict__ ph,
                              __nv_bfloat16* __restrict__ pl,
                              const float* __restrict__ xsrc, int xmode, int t,
                              int Cx, int C, int Cp, int cBeg,
                              const float* __restrict__ h,
                              const float* __restrict__ gates, int useR)
{
    const int half = (Cp - cBeg) >> 1;
    const int total2 = NB * half;
    int i = blockIdx.x * blockDim.x + threadIdx.x;
    if (i >= total2) return;
    int nb = i / half;
    int c = cBeg + (i - nb * half) * 2;
    float v0 = 0.f, v1 = 0.f;
    if (c < Cx) {
        if (xmode == 0) {
            int b = nb % BB, n = nb / BB;
            const float2 x2 = *(const float2*)&xsrc[(((long long)b * TT + t) * NN + n) * DIN + c];
            v0 = x2.x; v1 = x2.y;
        } else {
            const float2 x2 = *(const float2*)&xsrc[(long long)nb * Cx + c];
            v0 = x2.x; v1 = x2.y;
        }
    } else if (c < C) {
        int hc = c - Cx;
        const float2 h2 = *(const float2*)&h[(long long)nb * HH + hc];
        v0 = h2.x; v1 = h2.y;
        if (useR) {
            const float2 r2 = *(const float2*)&gates[(long long)nb * (2 * HH) + HH + hc];
            v0 *= r2.x; v1 *= r2.y;
        }
    }
    __nv_bfloat16 h0b, l0b, h1b, l1b;
    split2(v0, h0b, l0b); split2(v1, h1b, l1b);
    __nv_bfloat162 hh; hh.x = h0b; hh.y = h1b;
    __nv_bfloat162 ll; ll.x = l0b; ll.y = l1b;
    *(__nv_bfloat162*)&ph[(long long)nb * Cp + c] = hh;
    *(__nv_bfloat162*)&pl[(long long)nb * Cp + c] = ll;
}

__global__ void dec_proj_kernel(const float* __restrict__ h1,
                                const float* __restrict__ Wp,
                                const float* __restrict__ bp,
                                float* __restrict__ out,
                                float* __restrict__ xdec, int t)
{
    int row = blockIdx.x * blockDim.x + threadIdx.x;
    if (row >= NB) return;
    int n = row / BB, b = row % BB;
    float a0 = bp[0], a1 = bp[1];
    const float* hr = h1 + (long long)row * HH;
#pragma unroll 8
    for (int k = 0; k < HH; ++k) {
        float hv = hr[k];
        a0 += hv * Wp[k * 2]; a1 += hv * Wp[k * 2 + 1];
    }
    long long o = (((long long)b * TT + t) * NN + n) * 2;
    out[o] = a0; out[o + 1] = a1;
    xdec[(long long)row * 2] = a0; xdec[(long long)row * 2 + 1] = a1;
}

// ---------------------------------------------------------------------------
// host
// ---------------------------------------------------------------------------
static inline int gblocks(long long total, int tpb) {
    long long b = (total + tpb - 1) / tpb;
    if (b > 1048576) b = 1048576;
    return (int)b;
}

struct CellW {
    const __nv_bfloat16 *wgh, *wgl, *wch, *wcl;
    const float *bg, *bc;
    int Cx, Cp, Kd, Tk, hOnly;        // Kd = 5*Cp dense K, Tk = ceil64 chunks
    __nv_bfloat16 *fh, *fl;
    long long pstr;
};

static float* G_gates;

static void run_cell(const float* xsrc, int xmode, int t, float* h, const CellW& cw)
{
    const int Cp = cw.Cp, C = cw.Cx + HH;
    const int ldN = BB * Cp;
    const long long PS = cw.pstr;
    const long long SUPZ = 384LL * 384;
    const int cpp = Cp >> 3;          // 16B chunks per feats plane

    auto diffuse = [&](const __nv_bfloat16* srcH, const __nv_bfloat16* srcL,
                       long long bZ, __nv_bfloat16* dstH, __nv_bfloat16* dstL,
                       int hOnlyPass) {
        int cm = hOnlyPass ? 2 : 1, ca = hOnlyPass ? 1 : 0;
        dim3 gd(ldN / (128 * cm), 6, 2);
        pgemm_kernel<<<gd, 256, SMEM_TOTAL>>>(
            NN, 6, 384, 1 << 20,
            g_sh_p, g_sl_p, 384, 0, SUPZ,
            srcH, srcL, ldN, bZ,
            nullptr, dstH, dstL, ldN, 2 * PS,
            nullptr, 0, nullptr, cm, ca);
    };

    for (int pass = 0; pass < 2; ++pass) {
        const int ho = (pass == 1 && cw.hOnly) ? 1 : 0;
        const int cBeg = ho ? cw.Cx : 0;
        const int cgrid = (NB * ((Cp - cBeg) >> 1) + 255) / 256;
        concat_kernel<<<cgrid, 256>>>(cw.fh, cw.fl, xsrc, xmode, t,
                                      cw.Cx, C, Cp, cBeg, h, G_gates, pass);
        diffuse(cw.fh, cw.fl, 0, cw.fh + PS, cw.fl + PS, ho);
        diffuse(cw.fh + PS, cw.fl + PS, 2 * PS, cw.fh + 2 * PS, cw.fl + 2 * PS, ho);
        if (pass == 0) {
            dim3 g(2, NB / 64, 1);
            pgemm_kernel<<<g, 256, SMEM_TOTAL>>>(
                NB, cw.Tk, cw.Kd, cpp,
                cw.fh, cw.fl, Cp, PS, 0,
                cw.wgh, cw.wgl, 2 * HH, 0,
                G_gates, nullptr, nullptr, 2 * HH, 0,
                cw.bg, 1, nullptr, 1, 0);
        } else {
            dim3 g(1, NB / 64, 1);
            pgemm_kernel<<<g, 256, SMEM_TOTAL>>>(
                NB, cw.Tk, cw.Kd, cpp,
                cw.fh, cw.fl, Cp, PS, 0,
                cw.wch, cw.wcl, HH, 0,
                h, nullptr, nullptr, HH, 0,
                cw.bc, 3, G_gates, 1, 0);
        }
    }
}

extern "C" void kernel_launch(void* const* d_in, const int* in_sizes, int n_in,
                              void* d_out, int out_size)
{
    const float* source   = (const float*)d_in[0];
    const float* supports = (const float*)d_in[2];
    const float* Wp = (const float*)d_in[19];
    const float* bp = (const float*)d_in[20];
    float* out = (float*)d_out;

    cudaFuncSetAttribute(pgemm_kernel, cudaFuncAttributeMaxDynamicSharedMemorySize,
                         SMEM_TOTAL);

    __nv_bfloat16 *f0h, *f0l, *f1h, *f1l, *wh, *wl;
    float *h0, *h1, *xdec;
    cudaGetSymbolAddress((void**)&f0h, g_f0h);
    cudaGetSymbolAddress((void**)&f0l, g_f0l);
    cudaGetSymbolAddress((void**)&f1h, g_f1h);
    cudaGetSymbolAddress((void**)&f1l, g_f1l);
    cudaGetSymbolAddress((void**)&g_sh_p, g_sh);
    cudaGetSymbolAddress((void**)&g_sl_p, g_sl);
    cudaGetSymbolAddress((void**)&wh, g_wh);
    cudaGetSymbolAddress((void**)&wl, g_wl);
    cudaGetSymbolAddress((void**)&G_gates, g_gates);
    cudaGetSymbolAddress((void**)&h0, g_h0);
    cudaGetSymbolAddress((void**)&h1, g_h1);
    cudaGetSymbolAddress((void**)&xdec, g_xdec);

    // ---- prep: 3 launches ----
    split_sup_kernel<<<gblocks(2LL * NN * NN, 256), 256>>>(supports);
    WSpec8 ws;
    const int  idx[8]  = {3, 5, 7, 9, 11, 13, 15, 17};
    const long long off[8] = {OFF_E0G, OFF_E0C, OFF_E1G, OFF_E1C,
                              OFF_D0G, OFF_D0C, OFF_D1G, OFF_D1C};
    const int  Cs[8]   = {130, 130, 256, 256, 130, 130, 256, 256};
    const int  Cps[8]  = {CP0, CP0, CP1, CP1, CP0, CP0, CP1, CP1};
    const int  outs[8] = {256, 128, 256, 128, 256, 128, 256, 128};
    for (int i = 0; i < 8; ++i) {
        ws.src[i] = (const float*)d_in[idx[i]];
        ws.off[i] = off[i]; ws.C[i] = Cs[i]; ws.Cp[i] = Cps[i]; ws.outN[i] = outs[i];
    }
    split_w_kernel<<<dim3(512, 1, 8), 256>>>(ws, wh, wl);
    zero3_kernel<<<gblocks(2LL * NB * HH + NB * DIN, 256), 256>>>(
        h0, (long long)NB * HH, h1, (long long)NB * HH, xdec, (long long)NB * DIN);

    CellW enc0{ wh + OFF_E0G, wl + OFF_E0G, wh + OFF_E0C, wl + OFF_E0C,
                (const float*)d_in[4],  (const float*)d_in[6],
                DIN, CP0, KD0, KD0C / 64, 0, f0h, f0l, PSTR0 };
    CellW enc1{ wh + OFF_E1G, wl + OFF_E1G, wh + OFF_E1C, wl + OFF_E1C,
                (const float*)d_in[8],  (const float*)d_in[10],
                HH, CP1, KD1, KD1 / 64, 1, f1h, f1l, PSTR1 };
    CellW dec0{ wh + OFF_D0G, wl + OFF_D0G, wh + OFF_D0C, wl + OFF_D0C,
                (const float*)d_in[12], (const float*)d_in[14],
                DIN, CP0, KD0, KD0C / 64, 0, f0h, f0l, PSTR0 };
    CellW dec1{ wh + OFF_D1G, wl + OFF_D1G, wh + OFF_D1C, wl + OFF_D1C,
                (const float*)d_in[16], (const float*)d_in[18],
                HH, CP1, KD1, KD1 / 64, 1, f1h, f1l, PSTR1 };

    for (int t = 0; t < TT; ++t) {
        run_cell(source, 0, t, h0, enc0);
        run_cell(h0,     1, t, h1, enc1);
    }
    for (int t = 0; t < TT; ++t) {
        run_cell(xdec, 1, t, h0, dec0);
        run_cell(h0,   1, t, h1, dec1);
        dec_proj_kernel<<<(NB + 255) / 256, 256>>>(h1, Wp, bp, out, xdec, t);
    }
}

// round 17
// speedup vs baseline: 1.4635x; 1.0435x over previous
#include <cuda_runtime.h>
#include <cuda_bf16.h>
#include <mma.h>
#include <math.h>
#include <stdint.h>

using namespace nvcuda;

// Problem constants
#define BB  64
#define TT  12
#define NN  325
#define DIN 2
#define HH  128
#define KF  5

#define NB      (NN*BB)          // 20800
#define CP0     136              // padded C for layer0 (130 -> 136, 16B rows)
#define CP1     256              // layer1 C

#define PSTR0   (384LL*64*136)   // feats plane stride layer0
#define PSTR1   (384LL*64*256)

// dense-packed weight K extents (5 planes x Cp), covered to 64-chunks
#define KD0     680              // 5*136
#define KD0C    704              // ceil64
#define KD1     1280             // 5*256

#define SUPZ    (384LL*384)

// ---------------- static scratch (pads never written => stay zero) ----------
__device__ __align__(256) __nv_bfloat16 g_f0h[5*PSTR0], g_f0l[5*PSTR0];
__device__ __align__(256) __nv_bfloat16 g_f1h[5*PSTR1], g_f1l[5*PSTR1];
// 4 support planes: S0, S0^2, S1, S1^2 (384-padded, bf16 hi/lo)
__device__ __align__(256) __nv_bfloat16 g_sh[4*384*384], g_sl[4*384*384];
__device__ __align__(256) float g_s2f[2*325*325];      // S0^2, S1^2 fp32
__device__ __align__(256) __nv_bfloat16 g_wh[1523712],  g_wl[1523712];
__device__ float g_gates[(long long)NB*2*HH];
__device__ float g_h0[(long long)NB*HH];
__device__ float g_h1[(long long)NB*HH];
__device__ float g_xdec[(long long)NB*DIN];

static __nv_bfloat16 *g_sh_p = nullptr, *g_sl_p = nullptr;

// weight pool offsets (dense pack, tail rows zero)
#define OFF_E0G 0
#define OFF_E0C 180224
#define OFF_E1G 270336
#define OFF_E1C 598016
#define OFF_D0G 761856
#define OFF_D0C 942080
#define OFF_D1G 1032192
#define OFF_D1C 1359872

// ---------------------------------------------------------------------------
// helpers / prep
// ---------------------------------------------------------------------------
__device__ __forceinline__ void split2(float v, __nv_bfloat16& hi, __nv_bfloat16& lo) {
    hi = __float2bfloat16_rn(v);
    lo = __float2bfloat16_rn(v - __bfloat162float(hi));
}
__device__ __forceinline__ void cp16(uint32_t s, const void* g) {
    asm volatile("cp.async.cg.shared.global [%0], [%1], 16;\n" :: "r"(s), "l"(g));
}

// S^2 fp32: grid (11,11,2), block (32,8); 4 rows per thread
__global__ void s2_kernel(const float* __restrict__ sup) {
    __shared__ float sA[32][33], sB[32][33];
    const int zi = blockIdx.z;
    const float* S = sup + (long long)zi * 325 * 325;
    float* D = g_s2f + (long long)zi * 325 * 325;
    const int tx = threadIdx.x, ty = threadIdx.y;
    const int row0 = blockIdx.y * 32, col0 = blockIdx.x * 32;
    float acc[4] = {0.f, 0.f, 0.f, 0.f};
    for (int k0 = 0; k0 < 325; k0 += 32) {
#pragma unroll
        for (int q = 0; q < 4; ++q) {
            int r = row0 + ty + q * 8, c = k0 + tx;
            sA[ty + q * 8][tx] = (r < 325 && c < 325) ? S[r * 325 + c] : 0.f;
            int r2 = k0 + ty + q * 8, c2 = col0 + tx;
            sB[ty + q * 8][tx] = (r2 < 325 && c2 < 325) ? S[r2 * 325 + c2] : 0.f;
        }
        __syncthreads();
#pragma unroll 8
        for (int kk = 0; kk < 32; ++kk) {
            float b = sB[kk][tx];
#pragma unroll
            for (int q = 0; q < 4; ++q) acc[q] += sA[ty + q * 8][kk] * b;
        }
        __syncthreads();
    }
#pragma unroll
    for (int q = 0; q < 4; ++q) {
        int r = row0 + ty + q * 8, c = col0 + tx;
        if (r < 325 && c < 325) D[r * 325 + c] = acc[q];
    }
}

// split 4 support planes (S0, S0^2, S1, S1^2) into bf16 hi/lo, 384-padded
__global__ void split_sup4_kernel(const float* __restrict__ sup) {
    int i = blockIdx.x * blockDim.x + threadIdx.x;
    if (i >= 4 * NN * NN) return;
    int zi = i / (NN * NN), r = (i / NN) % NN, c = i % NN;
    const float* src = (zi & 1) ? (g_s2f + (long long)(zi >> 1) * 325 * 325)
                                : (sup   + (long long)(zi >> 1) * 325 * 325);
    __nv_bfloat16 hi, lo; split2(src[r * 325 + c], hi, lo);
    long long d = (long long)zi * 384 * 384 + (long long)r * 384 + c;
    g_sh[d] = hi; g_sl[d] = lo;
}

struct WSpec8 { const float* src[8]; long long off[8]; int C[8], Cp[8], outN[8]; };
__global__ void split_w_kernel(WSpec8 ws, __nv_bfloat16* dh, __nv_bfloat16* dl) {
    int z = blockIdx.z;
    const float* W = ws.src[z];
    int C = ws.C[z], Cp = ws.Cp[z], outN = ws.outN[z];
    long long total = (long long)KF * C * outN;
    for (long long i = blockIdx.x * (long long)blockDim.x + threadIdx.x; i < total;
         i += (long long)gridDim.x * blockDim.x) {
        int p = (int)(i / ((long long)C * outN));
        int rem = (int)(i % ((long long)C * outN));
        int k = rem / outN, o = rem % outN;
        __nv_bfloat16 hi, lo; split2(W[i], hi, lo);
        long long d = ws.off[z] + ((long long)p * Cp + k) * outN + o;
        dh[d] = hi; dl[d] = lo;
    }
}

__global__ void zero3_kernel(float* a, long long na, float* b, long long nb2,
                             float* c, long long nc) {
    long long tot = na + nb2 + nc;
    for (long long i = blockIdx.x * (long long)blockDim.x + threadIdx.x; i < tot;
         i += (long long)gridDim.x * blockDim.x) {
        if (i < na) a[i] = 0.f;
        else if (i < na + nb2) b[i - na] = 0.f;
        else c[i - na - nb2] = 0.f;
    }
}

// ---------------------------------------------------------------------------
// Pipelined bf16-pair GEMM (BM=64, BN=128, BK=64, 8 warps 2x4, occupancy 2).
//   C = act( A @ B + bias ),  A planar: global k -> (plane, kk) via cpp.
// B dense [Kcover x N].  Kt guards A tail (zero-filled).
// colBase = (blockIdx.x * colMul + colAdd) * 128  (h-only diffusion tiles).
// act: 0 = pair out (Ch/Cl), 1 = sigmoid->Cf, 2 = tanh->Cf,
//      3 = tanh + GRU fuse: Cf = z*Cf + (1-z)*tanh(v), z = gIn[gr*256+gc]
// ---------------------------------------------------------------------------
#define SMEM_A_BYTES 36864            // 2 stages * 2(hl) * 64 * 72 * 2B
#define SMEM_B_BYTES 69632            // 2 stages * 2(hl) * 64 * 136 * 2B
#define SMEM_TOTAL   (SMEM_A_BYTES + SMEM_B_BYTES)

__global__ __launch_bounds__(256, 2) void pgemm_kernel(
    int M, int T, int Kt, int cpp,
    const __nv_bfloat16* __restrict__ Ah, const __nv_bfloat16* __restrict__ Al,
    long long ldaA, long long pstrA, long long aZ,
    const __nv_bfloat16* __restrict__ Bh, const __nv_bfloat16* __restrict__ Bl,
    long long ldbB, long long bZ,
    float* __restrict__ Cf, __nv_bfloat16* __restrict__ Ch, __nv_bfloat16* __restrict__ Cl,
    long long ldc, long long cZ,
    const float* __restrict__ bias, int act, const float* __restrict__ gIn,
    int colMul, int colAdd)
{
    extern __shared__ char smem[];
    __nv_bfloat16* sA = (__nv_bfloat16*)smem;
    __nv_bfloat16* sB = (__nv_bfloat16*)(smem + SMEM_A_BYTES);
    const uint32_t sAu = (uint32_t)__cvta_generic_to_shared(sA);
    const uint32_t sBu = (uint32_t)__cvta_generic_to_shared(sB);

    const int tid = threadIdx.x;
    const int w = tid >> 5, lane = tid & 31;
    const int wm = w >> 2, wn = w & 3;      // 2x4 warps, 32x32 tiles
    const int rowBase = blockIdx.y * 64;
    const int colBase = (blockIdx.x * colMul + colAdd) * 128;

    Ah += (long long)blockIdx.z * aZ;  Al += (long long)blockIdx.z * aZ;
    Bh += (long long)blockIdx.z * bZ;  Bl += (long long)blockIdx.z * bZ;
    if (Ch) { Ch += (long long)blockIdx.z * cZ; Cl += (long long)blockIdx.z * cZ; }
    if (Cf) { Cf += (long long)blockIdx.z * cZ; }

    auto fill = [&](int stage, int it) {
        const int k0 = it * 64;
#pragma unroll
        for (int t = 0; t < 2; ++t) {                 // A: 512 16B chunks per h/l
            int id = tid + t * 256;
            int row = id >> 3, cc = id & 7;
            int gk = k0 + cc * 8;
            uint32_t s0 = sAu + (uint32_t)((((stage * 2 + 0) * 64 + row) * 72 + cc * 8) * 2);
            uint32_t s1 = sAu + (uint32_t)((((stage * 2 + 1) * 64 + row) * 72 + cc * 8) * 2);
            if (gk < Kt) {
                int chunk = gk >> 3;
                int p = chunk / cpp;
                int kk = chunk - p * cpp;
                long long ga = (long long)p * pstrA + (long long)(rowBase + row) * ldaA + kk * 8;
                cp16(s0, Ah + ga);
                cp16(s1, Al + ga);
            } else {
                float4 z = {0.f, 0.f, 0.f, 0.f};
                *(float4*)(sA + (((stage * 2 + 0) * 64 + row) * 72 + cc * 8)) = z;
                *(float4*)(sA + (((stage * 2 + 1) * 64 + row) * 72 + cc * 8)) = z;
            }
        }
#pragma unroll
        for (int t = 0; t < 4; ++t) {                 // B: 1024 16B chunks per h/l
            int id = tid + t * 256;
            int row = id >> 4, cc = id & 15;
            long long gb = (long long)(k0 + row) * ldbB + colBase + cc * 8;
            uint32_t s0 = sBu + (uint32_t)((((stage * 2 + 0) * 64 + row) * 136 + cc * 8) * 2);
            uint32_t s1 = sBu + (uint32_t)((((stage * 2 + 1) * 64 + row) * 136 + cc * 8) * 2);
            cp16(s0, Bh + gb);
            cp16(s1, Bl + gb);
        }
        asm volatile("cp.async.commit_group;\n" ::: "memory");
    };

    wmma::fragment<wmma::accumulator, 16, 16, 16, float> acc[2][2];
#pragma unroll
    for (int i = 0; i < 2; ++i)
#pragma unroll
        for (int j = 0; j < 2; ++j) wmma::fill_fragment(acc[i][j], 0.f);

    fill(0, 0);
    for (int it = 0; it < T; ++it) {
        if (it + 1 < T) {
            fill((it + 1) & 1, it + 1);
            asm volatile("cp.async.wait_group 1;\n" ::: "memory");
        } else {
            asm volatile("cp.async.wait_group 0;\n" ::: "memory");
        }
        __syncthreads();
        const int st = it & 1;
#pragma unroll
        for (int kk = 0; kk < 4; ++kk) {
            wmma::fragment<wmma::matrix_a, 16, 16, 16, __nv_bfloat16, wmma::row_major> a_h[2], a_l[2];
            wmma::fragment<wmma::matrix_b, 16, 16, 16, __nv_bfloat16, wmma::row_major> b_h[2], b_l[2];
#pragma unroll
            for (int i = 0; i < 2; ++i) {
                const int r = wm * 32 + i * 16;
                wmma::load_matrix_sync(a_h[i], sA + ((st * 2 + 0) * 64 + r) * 72 + kk * 16, 72);
                wmma::load_matrix_sync(a_l[i], sA + ((st * 2 + 1) * 64 + r) * 72 + kk * 16, 72);
            }
#pragma unroll
            for (int j = 0; j < 2; ++j) {
                const int c = wn * 32 + j * 16;
                wmma::load_matrix_sync(b_h[j], sB + ((st * 2 + 0) * 64 + kk * 16) * 136 + c, 136);
                wmma::load_matrix_sync(b_l[j], sB + ((st * 2 + 1) * 64 + kk * 16) * 136 + c, 136);
            }
#pragma unroll
            for (int i = 0; i < 2; ++i)
#pragma unroll
                for (int j = 0; j < 2; ++j) {
                    wmma::mma_sync(acc[i][j], a_h[i], b_h[j], acc[i][j]);
                    wmma::mma_sync(acc[i][j], a_h[i], b_l[j], acc[i][j]);
                    wmma::mma_sync(acc[i][j], a_l[i], b_h[j], acc[i][j]);
                }
        }
        __syncthreads();
    }

    // ---- epilogue: warp scratch (reuses sA region: 8 * 32*36 floats) ----
    float* scr = (float*)smem + w * (32 * 36);
#pragma unroll
    for (int i = 0; i < 2; ++i)
#pragma unroll
        for (int j = 0; j < 2; ++j)
            wmma::store_matrix_sync(scr + (i * 16) * 36 + j * 16, acc[i][j], 36,
                                    wmma::mem_row_major);
    __syncwarp();

#pragma unroll
    for (int t = 0; t < 16; ++t) {
        int e = lane + t * 32;
        int r = e >> 4, c = (e & 15) * 2;
        int gr = rowBase + wm * 32 + r;
        if (gr >= M) continue;
        int gc = colBase + wn * 32 + c;
        float v0 = scr[r * 36 + c];
        float v1 = scr[r * 36 + c + 1];
        if (bias) { v0 += bias[gc]; v1 += bias[gc + 1]; }
        if (act == 1) {
            v0 = 1.f / (1.f + expf(-v0)); v1 = 1.f / (1.f + expf(-v1));
        } else if (act == 2) {
            v0 = tanhf(v0); v1 = tanhf(v1);
        } else if (act == 3) {
            v0 = tanhf(v0); v1 = tanhf(v1);
            float z0 = gIn[(long long)gr * (2 * HH) + gc];
            float z1 = gIn[(long long)gr * (2 * HH) + gc + 1];
            long long ho = (long long)gr * ldc + gc;
            v0 = z0 * Cf[ho]     + (1.f - z0) * v0;
            v1 = z1 * Cf[ho + 1] + (1.f - z1) * v1;
        }
        if (Ch) {
            __nv_bfloat16 h0b, l0b, h1b, l1b;
            split2(v0, h0b, l0b); split2(v1, h1b, l1b);
            __nv_bfloat162 hh; hh.x = h0b; hh.y = h1b;
            __nv_bfloat162 ll; ll.x = l0b; ll.y = l1b;
            *(__nv_bfloat162*)&Ch[(long long)gr * ldc + gc] = hh;
            *(__nv_bfloat162*)&Cl[(long long)gr * ldc + gc] = ll;
        } else {
            float2 f; f.x = v0; f.y = v1;
            *(float2*)&Cf[(long long)gr * ldc + gc] = f;
        }
    }
}

// ---------------------------------------------------------------------------
// concat (vectorized, channel range [cBeg, Cp)): plane 0 of feats (hi/lo).
// ---------------------------------------------------------------------------
__global__ void concat_kernel(__nv_bfloat16* __restrict__ ph,
                              __nv_bfloat16* __restrict__ pl,
                              const float* __restrict__ xsrc, int xmode, int t,
                              int Cx, int C, int Cp, int cBeg,
                              const float* __restrict__ h,
                              const float* __restrict__ gates, int useR)
{
    const int half = (Cp - cBeg) >> 1;
    const int total2 = NB * half;
    int i = blockIdx.x * blockDim.x + threadIdx.x;
    if (i >= total2) return;
    int nb = i / half;
    int c = cBeg + (i - nb * half) * 2;
    float v0 = 0.f, v1 = 0.f;
    if (c < Cx) {
        if (xmode == 0) {
            int b = nb % BB, n = nb / BB;
            const float2 x2 = *(const float2*)&xsrc[(((long long)b * TT + t) * NN + n) * DIN + c];
            v0 = x2.x; v1 = x2.y;
        } else {
            const float2 x2 = *(const float2*)&xsrc[(long long)nb * Cx + c];
            v0 = x2.x; v1 = x2.y;
        }
    } else if (c < C) {
        int hc = c - Cx;
        const float2 h2 = *(const float2*)&h[(long long)nb * HH + hc];
        v0 = h2.x; v1 = h2.y;
        if (useR) {
            const float2 r2 = *(const float2*)&gates[(long long)nb * (2 * HH) + HH + hc];
            v0 *= r2.x; v1 *= r2.y;
        }
    }
    __nv_bfloat16 h0b, l0b, h1b, l1b;
    split2(v0, h0b, l0b); split2(v1, h1b, l1b);
    __nv_bfloat162 hh; hh.x = h0b; hh.y = h1b;
    __nv_bfloat162 ll; ll.x = l0b; ll.y = l1b;
    *(__nv_bfloat162*)&ph[(long long)nb * Cp + c] = hh;
    *(__nv_bfloat162*)&pl[(long long)nb * Cp + c] = ll;
}

__global__ void dec_proj_kernel(const float* __restrict__ h1,
                                const float* __restrict__ Wp,
                                const float* __restrict__ bp,
                                float* __restrict__ out,
                                float* __restrict__ xdec, int t)
{
    int row = blockIdx.x * blockDim.x + threadIdx.x;
    if (row >= NB) return;
    int n = row / BB, b = row % BB;
    float a0 = bp[0], a1 = bp[1];
    const float* hr = h1 + (long long)row * HH;
#pragma unroll 8
    for (int k = 0; k < HH; ++k) {
        float hv = hr[k];
        a0 += hv * Wp[k * 2]; a1 += hv * Wp[k * 2 + 1];
    }
    long long o = (((long long)b * TT + t) * NN + n) * 2;
    out[o] = a0; out[o + 1] = a1;
    xdec[(long long)row * 2] = a0; xdec[(long long)row * 2 + 1] = a1;
}

// ---------------------------------------------------------------------------
// host
// ---------------------------------------------------------------------------
static inline int gblocks(long long total, int tpb) {
    long long b = (total + tpb - 1) / tpb;
    if (b > 1048576) b = 1048576;
    return (int)b;
}

struct CellW {
    const __nv_bfloat16 *wgh, *wgl, *wch, *wcl;
    const float *bg, *bc;
    int Cx, Cp, Kd, Tk, hOnly;
    __nv_bfloat16 *fh, *fl;
    long long pstr;
};

static float* G_gates;

static void run_cell(const float* xsrc, int xmode, int t, float* h, const CellW& cw)
{
    const int Cp = cw.Cp, C = cw.Cx + HH;
    const int ldN = BB * Cp;
    const long long PS = cw.pstr;
    const int cpp = Cp >> 3;          // 16B chunks per feats plane

    for (int pass = 0; pass < 2; ++pass) {
        const int ho = (pass == 1 && cw.hOnly) ? 1 : 0;
        const int cBeg = ho ? cw.Cx : 0;
        const int cgrid = (NB * ((Cp - cBeg) >> 1) + 255) / 256;
        concat_kernel<<<cgrid, 256>>>(cw.fh, cw.fl, xsrc, xmode, t,
                                      cw.Cx, C, Cp, cBeg, h, G_gates, pass);
        // single diffusion launch: z = 4 support planes {S0, S0^2, S1, S1^2},
        // all reading plane 0, writing planes 1..4
        {
            int cm = ho ? 2 : 1, ca = ho ? 1 : 0;
            dim3 gd(ldN / (128 * cm), 6, 4);
            pgemm_kernel<<<gd, 256, SMEM_TOTAL>>>(
                NN, 6, 384, 1 << 20,
                g_sh_p, g_sl_p, 384, 0, SUPZ,
                cw.fh, cw.fl, ldN, 0,
                nullptr, cw.fh + PS, cw.fl + PS, ldN, PS,
                nullptr, 0, nullptr, cm, ca);
        }
        if (pass == 0) {
            dim3 g(2, NB / 64, 1);
            pgemm_kernel<<<g, 256, SMEM_TOTAL>>>(
                NB, cw.Tk, cw.Kd, cpp,
                cw.fh, cw.fl, Cp, PS, 0,
                cw.wgh, cw.wgl, 2 * HH, 0,
                G_gates, nullptr, nullptr, 2 * HH, 0,
                cw.bg, 1, nullptr, 1, 0);
        } else {
            dim3 g(1, NB / 64, 1);
            pgemm_kernel<<<g, 256, SMEM_TOTAL>>>(
                NB, cw.Tk, cw.Kd, cpp,
                cw.fh, cw.fl, Cp, PS, 0,
                cw.wch, cw.wcl, HH, 0,
                h, nullptr, nullptr, HH, 0,
                cw.bc, 3, G_gates, 1, 0);
        }
    }
}

extern "C" void kernel_launch(void* const* d_in, const int* in_sizes, int n_in,
                              void* d_out, int out_size)
{
    const float* source   = (const float*)d_in[0];
    const float* supports = (const float*)d_in[2];
    const float* Wp = (const float*)d_in[19];
    const float* bp = (const float*)d_in[20];
    float* out = (float*)d_out;

    cudaFuncSetAttribute(pgemm_kernel, cudaFuncAttributeMaxDynamicSharedMemorySize,
                         SMEM_TOTAL);

    __nv_bfloat16 *f0h, *f0l, *f1h, *f1l, *wh, *wl;
    float *h0, *h1, *xdec;
    cudaGetSymbolAddress((void**)&f0h, g_f0h);
    cudaGetSymbolAddress((void**)&f0l, g_f0l);
    cudaGetSymbolAddress((void**)&f1h, g_f1h);
    cudaGetSymbolAddress((void**)&f1l, g_f1l);
    cudaGetSymbolAddress((void**)&g_sh_p, g_sh);
    cudaGetSymbolAddress((void**)&g_sl_p, g_sl);
    cudaGetSymbolAddress((void**)&wh, g_wh);
    cudaGetSymbolAddress((void**)&wl, g_wl);
    cudaGetSymbolAddress((void**)&G_gates, g_gates);
    cudaGetSymbolAddress((void**)&h0, g_h0);
    cudaGetSymbolAddress((void**)&h1, g_h1);
    cudaGetSymbolAddress((void**)&xdec, g_xdec);

    // ---- prep: 4 launches ----
    s2_kernel<<<dim3(11, 11, 2), dim3(32, 8)>>>(supports);
    split_sup4_kernel<<<gblocks(4LL * NN * NN, 256), 256>>>(supports);
    WSpec8 ws;
    const int  idx[8]  = {3, 5, 7, 9, 11, 13, 15, 17};
    const long long off[8] = {OFF_E0G, OFF_E0C, OFF_E1G, OFF_E1C,
                              OFF_D0G, OFF_D0C, OFF_D1G, OFF_D1C};
    const int  Cs[8]   = {130, 130, 256, 256, 130, 130, 256, 256};
    const int  Cps[8]  = {CP0, CP0, CP1, CP1, CP0, CP0, CP1, CP1};
    const int  outs[8] = {256, 128, 256, 128, 256, 128, 256, 128};
    for (int i = 0; i < 8; ++i) {
        ws.src[i] = (const float*)d_in[idx[i]];
        ws.off[i] = off[i]; ws.C[i] = Cs[i]; ws.Cp[i] = Cps[i]; ws.outN[i] = outs[i];
    }
    split_w_kernel<<<dim3(512, 1, 8), 256>>>(ws, wh, wl);
    zero3_kernel<<<gblocks(2LL * NB * HH + NB * DIN, 256), 256>>>(
        h0, (long long)NB * HH, h1, (long long)NB * HH, xdec, (long long)NB * DIN);

    CellW enc0{ wh + OFF_E0G, wl + OFF_E0G, wh + OFF_E0C, wl + OFF_E0C,
                (const float*)d_in[4],  (const float*)d_in[6],
                DIN, CP0, KD0, KD0C / 64, 0, f0h, f0l, PSTR0 };
    CellW enc1{ wh + OFF_E1G, wl + OFF_E1G, wh + OFF_E1C, wl + OFF_E1C,
                (const float*)d_in[8],  (const float*)d_in[10],
                HH, CP1, KD1, KD1 / 64, 1, f1h, f1l, PSTR1 };
    CellW dec0{ wh + OFF_D0G, wl + OFF_D0G, wh + OFF_D0C, wl + OFF_D0C,
                (const float*)d_in[12], (const float*)d_in[14],
                DIN, CP0, KD0, KD0C / 64, 0, f0h, f0l, PSTR0 };
    CellW dec1{ wh + OFF_D1G, wl + OFF_D1G, wh + OFF_D1C, wl + OFF_D1C,
                (const float*)d_in[16], (const float*)d_in[18],
                HH, CP1, KD1, KD1 / 64, 1, f1h, f1l, PSTR1 };

    for (int t = 0; t < TT; ++t) {
        run_cell(source, 0, t, h0, enc0);
        run_cell(h0,     1, t, h1, enc1);
    }
    for (int t = 0; t < TT; ++t) {
        run_cell(xdec, 1, t, h0, dec0);
        run_cell(h0,   1, t, h1, dec1);
        dec_proj_kernel<<<(NB + 255) / 256, 256>>>(h1, Wp, bp, out, xdec, t);
    }
}